// round 11
// baseline (speedup 1.0000x reference)
#include <cuda_runtime.h>
#include <cuda_fp16.h>
#include <math.h>
#include <stdint.h>

#define H 256
#define T 512
#define B 64
#define M_TOT (B*T)   // 32768

// ---------------- scratch (static device globals; no allocation) ----------------
__device__ float d_Wfq[H*H];            // W1[3H:4H] + W1[4H:5H]
__device__ float d_Wabs[H*H];           // W1[5H:6H] + W1[6H:7H]
__device__ float d_attpre[B*H];         // q@(W1[H:2H]+W1[2H:3H]) + b1
__device__ float d_ms[B];               // q . Ws[0:H]
__device__ float d_me[B];               // q . We[0:H]
__device__ float d_V[M_TOT*H];          // tanh(feats@W1 + b1)
__device__ float d_att[M_TOT];          // logits
__device__ float d_g[M_TOT];            // softmax gates
__device__ float d_xrh[(size_t)M_TOT*2*H]; // [m][0:256]=x@Wr+br, [256:512]=x@Wh+bh
__device__ __half d_Ur16[H*H];          // fp16 copy of Ur  [k][j]
__device__ __half d_Uh16[H*H];          // fp16 copy of Uh  [k][j]

// ---------------- small PTX helpers ----------------
static __device__ __forceinline__ uint32_t s2u(const void* p) {
    return (uint32_t)__cvta_generic_to_shared(p);
}
static __device__ __forceinline__ uint32_t mapa_peer(uint32_t a, uint32_t r) {
    uint32_t d;
    asm("mapa.shared::cluster.u32 %0, %1, %2;" : "=r"(d) : "r"(a), "r"(r));
    return d;
}
static __device__ __forceinline__ void st_cluster_u32(uint32_t addr, uint32_t v) {
    asm volatile("st.shared::cluster.u32 [%0], %1;" :: "r"(addr), "r"(v) : "memory");
}
static __device__ __forceinline__ void st_cluster_u64(uint32_t addr, uint64_t v) {
    asm volatile("st.shared::cluster.b64 [%0], %1;" :: "r"(addr), "l"(v) : "memory");
}
static __device__ __forceinline__ void arrive_cluster(uint32_t rbar) {
    asm volatile("mbarrier.arrive.release.cluster.shared::cluster.b64 _, [%0];"
                 :: "r"(rbar) : "memory");
}
static __device__ __forceinline__ void mbar_init(uint32_t bar, uint32_t cnt) {
    asm volatile("mbarrier.init.shared.b64 [%0], %1;" :: "r"(bar), "r"(cnt) : "memory");
}
static __device__ __forceinline__ void mbar_wait_cluster(uint32_t bar, uint32_t parity) {
    uint32_t done;
    asm volatile(
        "{\n\t.reg .pred p;\n\t"
        "mbarrier.try_wait.parity.acquire.cluster.shared::cta.b64 p, [%1], %2;\n\t"
        "selp.b32 %0, 1, 0, p;\n\t}"
        : "=r"(done) : "r"(bar), "r"(parity) : "memory");
    while (!done) {
        asm volatile(
            "{\n\t.reg .pred p;\n\t"
            "mbarrier.try_wait.parity.acquire.cluster.shared::cta.b64 p, [%1], %2, 0x989680;\n\t"
            "selp.b32 %0, 1, 0, p;\n\t}"
            : "=r"(done) : "r"(bar), "r"(parity) : "memory");
    }
}
static __device__ __forceinline__ void cluster_sync_all() {
    asm volatile("barrier.cluster.arrive.aligned;" ::: "memory");
    asm volatile("barrier.cluster.wait.aligned;" ::: "memory");
}

// ---------------- K0: combine W1 slices ----------------
__global__ __launch_bounds__(256) void prep_w_kernel(const float* __restrict__ W1)
{
    int i = blockIdx.x * 256 + threadIdx.x;           // 65536 total
    d_Wfq[i]  = W1[196608 + i] + W1[262144 + i];      // rows [3H,4H) + [4H,5H)
    d_Wabs[i] = W1[327680 + i] + W1[393216 + i];      // rows [5H,6H) + [6H,7H)
}

// ---------------- K0b: fp16 conversion of Ur/Uh ----------------
__global__ __launch_bounds__(256) void prep_u16_kernel(
    const float* __restrict__ Ur, const float* __restrict__ Uh)
{
    int i = blockIdx.x * 256 + threadIdx.x;           // 65536 total
    d_Ur16[i] = __float2half(Ur[i]);
    d_Uh16[i] = __float2half(Uh[i]);
}

// ---------------- K1: per-batch precompute ----------------
__global__ __launch_bounds__(256) void prep_batch_kernel(
    const float* __restrict__ qv, const float* __restrict__ W1,
    const float* __restrict__ b1, const float* __restrict__ Ws,
    const float* __restrict__ We)
{
    const int b = blockIdx.x, j = threadIdx.x;
    __shared__ float qs[H];
    __shared__ float redS[8], redE[8];
    qs[j] = qv[b*H + j];
    __syncthreads();

    float acc = 0.f;
#pragma unroll 8
    for (int k = 0; k < H; ++k)
        acc += qs[k] * (W1[(H + k)*H + j] + W1[(2*H + k)*H + j]);
    d_attpre[b*H + j] = acc + b1[j];

    float ps = qs[j] * Ws[j];
    float pe = qs[j] * We[j];
#pragma unroll
    for (int off = 16; off; off >>= 1) {
        ps += __shfl_xor_sync(0xffffffffu, ps, off);
        pe += __shfl_xor_sync(0xffffffffu, pe, off);
    }
    if ((j & 31) == 0) { redS[j >> 5] = ps; redE[j >> 5] = pe; }
    __syncthreads();
    if (j == 0) {
        float s = 0.f, se = 0.f;
#pragma unroll
        for (int w = 0; w < 8; ++w) { s += redS[w]; se += redE[w]; }
        d_ms[b] = s;
        d_me[b] = se;
    }
}

// ---------------- K2a: attention GEMM (M=32768, K=768 virtual, N=256) ----------------
__global__ __launch_bounds__(256) void gemm_att_kernel(
    const float* __restrict__ fact, const float* __restrict__ qv,
    const float* __restrict__ W1)
{
    __shared__ float As[16][64];
    __shared__ float Bs[16][64];
    const int tid = threadIdx.x;
    const int m0 = blockIdx.x * 64;        // 64 consecutive rows: same batch (512/64=8)
    const int n0 = blockIdx.y * 64;
    const int b  = m0 >> 9;
    const int tx = tid & 15, ty = tid >> 4;
    const int arow = tid >> 2, akq = (tid & 3) * 4;
    const int bkr = tid >> 4,  bjc = (tid & 15) * 4;

    float acc[4][4] = {};

    for (int sel = 0; sel < 3; ++sel) {
        const float* __restrict__ W = (sel == 0) ? W1 : (sel == 1) ? d_Wfq : d_Wabs;
        for (int kp0 = 0; kp0 < H; kp0 += 16) {
            float4 f4 = *(const float4*)(fact + (m0 + arow)*H + kp0 + akq);
            float4 q4 = *(const float4*)(qv + b*H + kp0 + akq);
            float4 v4;
            if (sel == 0)      v4 = f4;
            else if (sel == 1) { v4.x = f4.x*q4.x; v4.y = f4.y*q4.y;
                                 v4.z = f4.z*q4.z; v4.w = f4.w*q4.w; }
            else               { v4.x = fabsf(f4.x - q4.x); v4.y = fabsf(f4.y - q4.y);
                                 v4.z = fabsf(f4.z - q4.z); v4.w = fabsf(f4.w - q4.w); }
            As[akq + 0][arow] = v4.x;
            As[akq + 1][arow] = v4.y;
            As[akq + 2][arow] = v4.z;
            As[akq + 3][arow] = v4.w;
            *(float4*)&Bs[bkr][bjc] = *(const float4*)(W + (kp0 + bkr)*H + n0 + bjc);
            __syncthreads();
#pragma unroll
            for (int k = 0; k < 16; ++k) {
                float4 a  = *(const float4*)&As[k][ty * 4];
                float4 bb = *(const float4*)&Bs[k][tx * 4];
                acc[0][0] += a.x*bb.x; acc[0][1] += a.x*bb.y; acc[0][2] += a.x*bb.z; acc[0][3] += a.x*bb.w;
                acc[1][0] += a.y*bb.x; acc[1][1] += a.y*bb.y; acc[1][2] += a.y*bb.z; acc[1][3] += a.y*bb.w;
                acc[2][0] += a.z*bb.x; acc[2][1] += a.z*bb.y; acc[2][2] += a.z*bb.z; acc[2][3] += a.z*bb.w;
                acc[3][0] += a.w*bb.x; acc[3][1] += a.w*bb.y; acc[3][2] += a.w*bb.z; acc[3][3] += a.w*bb.w;
            }
            __syncthreads();
        }
    }
#pragma unroll
    for (int i = 0; i < 4; ++i) {
        int m = m0 + ty * 4 + i;
#pragma unroll
        for (int jj = 0; jj < 4; ++jj) {
            int n = n0 + tx * 4 + jj;
            d_V[m*H + n] = tanhf(acc[i][jj] + d_attpre[b*H + n]);
        }
    }
}

// ---------------- K2b: att[m] = V[m] . W2 + b2 ----------------
__global__ __launch_bounds__(256) void att_dot_kernel(
    const float* __restrict__ W2, const float* __restrict__ b2)
{
    const int row  = blockIdx.x * 8 + (threadIdx.x >> 5);
    const int lane = threadIdx.x & 31;
    float s = 0.f;
#pragma unroll
    for (int i = 0; i < 8; ++i) {
        int jj = lane + i * 32;
        s += d_V[row*H + jj] * W2[jj];
    }
#pragma unroll
    for (int off = 16; off; off >>= 1) s += __shfl_xor_sync(0xffffffffu, s, off);
    if (lane == 0) d_att[row] = s + b2[0];
}

// ---------------- K4: softmax over T per batch ----------------
__global__ __launch_bounds__(256) void softmax_kernel()
{
    const int b = blockIdx.x, tid = threadIdx.x;
    __shared__ float sd[256];
    float x0 = d_att[b*T + tid];
    float x1 = d_att[b*T + 256 + tid];
    sd[tid] = fmaxf(x0, x1);
    __syncthreads();
    for (int s = 128; s; s >>= 1) {
        if (tid < s) sd[tid] = fmaxf(sd[tid], sd[tid + s]);
        __syncthreads();
    }
    const float M = sd[0];
    __syncthreads();
    float e0 = expf(x0 - M), e1 = expf(x1 - M);
    sd[tid] = e0 + e1;
    __syncthreads();
    for (int s = 128; s; s >>= 1) {
        if (tid < s) sd[tid] += sd[tid + s];
        __syncthreads();
    }
    const float inv = 1.0f / sd[0];
    d_g[b*T + tid]       = e0 * inv;
    d_g[b*T + 256 + tid] = e1 * inv;
}

// ---------------- K3: XRH GEMM (M=32768, K=256, N=512 = [Wr|Wh]) + bias ----------------
__global__ __launch_bounds__(256) void gemm_xrh_kernel(
    const float* __restrict__ fact, const float* __restrict__ Wr,
    const float* __restrict__ Wh,   const float* __restrict__ br,
    const float* __restrict__ bh)
{
    __shared__ float As[16][64];
    __shared__ float Bs[16][64];
    const int tid = threadIdx.x;
    const int m0 = blockIdx.x * 64;
    const int n0 = blockIdx.y * 64;
    const int tx = tid & 15, ty = tid >> 4;
    const int arow = tid >> 2, akq = (tid & 3) * 4;
    const int bkr = tid >> 4,  bjc = (tid & 15) * 4;

    const bool isR = (n0 < H);
    const float* __restrict__ W    = isR ? Wr : Wh;
    const float* __restrict__ bias = isR ? br : bh;
    const int nb = isR ? n0 : n0 - H;

    float acc[4][4] = {};
    for (int k0 = 0; k0 < H; k0 += 16) {
        float4 f4 = *(const float4*)(fact + (m0 + arow)*H + k0 + akq);
        As[akq + 0][arow] = f4.x;
        As[akq + 1][arow] = f4.y;
        As[akq + 2][arow] = f4.z;
        As[akq + 3][arow] = f4.w;
        *(float4*)&Bs[bkr][bjc] = *(const float4*)(W + (k0 + bkr)*H + nb + bjc);
        __syncthreads();
#pragma unroll
        for (int k = 0; k < 16; ++k) {
            float4 a  = *(const float4*)&As[k][ty * 4];
            float4 bb = *(const float4*)&Bs[k][tx * 4];
            acc[0][0] += a.x*bb.x; acc[0][1] += a.x*bb.y; acc[0][2] += a.x*bb.z; acc[0][3] += a.x*bb.w;
            acc[1][0] += a.y*bb.x; acc[1][1] += a.y*bb.y; acc[1][2] += a.y*bb.z; acc[1][3] += a.y*bb.w;
            acc[2][0] += a.z*bb.x; acc[2][1] += a.z*bb.y; acc[2][2] += a.z*bb.z; acc[2][3] += a.z*bb.w;
            acc[3][0] += a.w*bb.x; acc[3][1] += a.w*bb.y; acc[3][2] += a.w*bb.z; acc[3][3] += a.w*bb.w;
        }
        __syncthreads();
    }
#pragma unroll
    for (int i = 0; i < 4; ++i) {
        int m = m0 + ty * 4 + i;
#pragma unroll
        for (int jj = 0; jj < 4; ++jj) {
            int n = n0 + tx * 4 + jj;
            d_xrh[(size_t)m * (2*H) + n] = acc[i][jj] + bias[nb + tx*4 + jj];
        }
    }
}

// ---------------- K5: GRU recurrence — 2-CTA cluster per batch ----------------
// grid=128, cluster=2: CTA rank r owns output columns [r*128, r*128+128).
// Weight slice per CTA = 128 KB fp16 -> fully L1-resident (no per-step L2 traffic).
// Matvec: 16 warps, warp kg owns k-slice of 16, lane owns 4 columns.
// fp16 HFMA2 accumulation in even/odd 8-term chains, drained to fp32 in smem.
// Cross-CTA rh/h exchange via DSMEM stores + mbarrier (release/acquire, cluster scope).
__device__ __forceinline__ void matvec_slice(
    const __half* __restrict__ Wbase, const __half2* __restrict__ src,
    int k0, int jbase, int j0, float* __restrict__ redrow)
{
    __half2 aE0 = __float2half2_rn(0.f), aE1 = aE0, aO0 = aE0, aO1 = aE0;
    const __half* Wp = Wbase + k0 * H + jbase + j0;
#pragma unroll
    for (int kk = 0; kk < 16; ++kk) {
        uint2 w = *(const uint2*)(Wp + kk * H);
        __half2 hk = src[k0 + kk];
        __half2 w0 = *(__half2*)&w.x;
        __half2 w1 = *(__half2*)&w.y;
        if (kk & 1) { aO0 = __hfma2(w0, hk, aO0); aO1 = __hfma2(w1, hk, aO1); }
        else        { aE0 = __hfma2(w0, hk, aE0); aE1 = __hfma2(w1, hk, aE1); }
    }
    float2 e0 = __half22float2(aE0), o0 = __half22float2(aO0);
    float2 e1 = __half22float2(aE1), o1 = __half22float2(aO1);
    *(float4*)redrow = make_float4(e0.x + o0.x, e0.y + o0.y, e1.x + o1.x, e1.y + o1.y);
}

__global__ __launch_bounds__(512) __cluster_dims__(2, 1, 1)
void recurrence_kernel(
    const int* __restrict__ input_len,
    const float* __restrict__ Ws, const float* __restrict__ bs,
    const float* __restrict__ We, const float* __restrict__ be,
    float* __restrict__ out)
{
    const int b     = blockIdx.x >> 1;
    const int rank  = blockIdx.x & 1;
    const int tid   = threadIdx.x;
    const int kg    = tid >> 5;          // warp = k-group (16 k each)
    const int jl    = tid & 31;
    const int j0    = jl * 4;            // 4 cols per lane within slice
    const int k0    = kg * 16;
    const int jbase = rank * 128;

    __shared__ float   h_s[128];         // own columns, fp32 master
    __shared__ __half2 h2_s[H];          // full h, broadcast pairs
    __shared__ __half2 rh2_s[H];         // full r*h, broadcast pairs
    __shared__ float   red[16][128];
    __shared__ float   redS[4], redE[4];
    __shared__ float2  peer_part;        // rank0 receives rank1's output partials
    __shared__ __align__(8) uint64_t bar_rh, bar_h;

    const uint32_t u_bar_rh = s2u(&bar_rh);
    const uint32_t u_bar_h  = s2u(&bar_h);
    const uint32_t peer     = rank ^ 1;
    const uint32_t r_bar_rh = mapa_peer(u_bar_rh, peer);
    const uint32_t r_bar_h  = mapa_peer(u_bar_h, peer);

    if (tid == 0) {
        mbar_init(u_bar_rh, 128);
        mbar_init(u_bar_h, 128);
    }
    if (tid < 128) h_s[tid] = 0.f;
    if (tid < H) {
        h2_s[tid]  = __float2half2_rn(0.f);
        rh2_s[tid] = __float2half2_rn(0.f);
    }
    __syncthreads();
    cluster_sync_all();                  // barrier inits visible cluster-wide

    const int len = input_len[b];
    const float* __restrict__ xb = d_xrh + (size_t)b * T * (2*H);

    // per-thread state for the 128 "column owner" threads
    float ws2 = 0.f, we2 = 0.f;
    float xr_c = 0.f, xh_c = 0.f, g_c = 0.f;
    uint32_t r_rh = 0, r_h2 = 0;
    const int jg = jbase + tid;
    if (tid < 128) {
        ws2 = Ws[H + jg];
        we2 = We[H + jg];
        xr_c = xb[jg];
        xh_c = xb[256 + jg];
        g_c  = d_g[b*T];
        r_rh = mapa_peer(s2u(&rh2_s[jg]), peer);
        r_h2 = mapa_peer(s2u(&h2_s[jg]), peer);
    }
    const uint32_t r_part = mapa_peer(s2u(&peer_part), peer);
    float msb = 0.f, meb = 0.f, myPS = 0.f, myPE = 0.f;
    if (tid == 0) { msb = d_ms[b] + bs[0]; meb = d_me[b] + be[0]; }

    float hj = 0.f, xr_n = 0.f, xh_n = 0.f, g_n = 0.f;

    const int nsteps = len;              // t >= len: h frozen, e = 0 -> constant outputs
    for (int t = 0; t < nsteps; ++t) {
        // ---- p1: partial h @ Ur (reads full h2_s)
        matvec_slice(d_Ur16, h2_s, k0, jbase, j0, &red[kg][j0]);
        __syncthreads();

        // ---- p2: r, rh for own columns; send rh half to peer
        if (tid < 128) {
            float s = xr_c;
#pragma unroll
            for (int g = 0; g < 16; ++g) s += red[g][tid];
            const float r = 1.0f / (1.0f + expf(-s));
            hj = h_s[tid];
            const float rhv = r * hj;
            __half2 p = __float2half2_rn(rhv);
            rh2_s[jg] = p;
            st_cluster_u32(r_rh, *(uint32_t*)&p);
            // prefetch next step's x / g while latency is free
            const int tn = (t + 1 < T) ? (t + 1) : (T - 1);
            xr_n = xb[tn*(2*H) + jg];
            xh_n = xb[tn*(2*H) + 256 + jg];
            g_n  = d_g[b*T + tn];
            arrive_cluster(r_bar_rh);
        }
        __syncthreads();                       // local rh2_s visible
        mbar_wait_cluster(u_bar_rh, t & 1);    // peer rh2_s half arrived

        // ---- p3: partial rh @ Uh (reads full rh2_s)
        matvec_slice(d_Uh16, rh2_s, k0, jbase, j0, &red[kg][j0]);
        __syncthreads();

        // ---- p4: h update, output partial dots; send h half to peer
        if (tid < 128) {
            float s = xh_c;
#pragma unroll
            for (int g = 0; g < 16; ++g) s += red[g][tid];
            const float hc = tanhf(s);
            const float hn = fmaf(g_c, hc - hj, hj);   // t < len always here
            h_s[tid] = hn;
            __half2 p = __float2half2_rn(hn);
            h2_s[jg] = p;
            st_cluster_u32(r_h2, *(uint32_t*)&p);
            float ps = hn * ws2, pe = hn * we2;
#pragma unroll
            for (int off = 16; off; off >>= 1) {
                ps += __shfl_xor_sync(0xffffffffu, ps, off);
                pe += __shfl_xor_sync(0xffffffffu, pe, off);
            }
            if (jl == 0) { redS[tid >> 5] = ps; redE[tid >> 5] = pe; }
            if (tid != 0) arrive_cluster(r_bar_h);
            xr_c = xr_n; xh_c = xh_n; g_c = g_n;
        }
        __syncthreads();                       // redS/redE + local h2_s visible
        if (tid == 0) {
            const float s  = redS[0] + redS[1] + redS[2] + redS[3];
            const float se = redE[0] + redE[1] + redE[2] + redE[3];
            if (rank) {
                float2 pp = make_float2(s, se);
                st_cluster_u64(r_part, *(uint64_t*)&pp);
            } else {
                myPS = s; myPE = se;
            }
            arrive_cluster(r_bar_h);           // release covers h store (+ partials)
        }
        mbar_wait_cluster(u_bar_h, t & 1);     // peer h half (+ partials) arrived
        if (rank == 0 && tid == 0) {
            out[b*T + t]       = tanhf(msb + myPS + peer_part.x);
            out[B*T + b*T + t] = tanhf(meb + myPE + peer_part.y);
        }
    }

    // tail: t in [len, T) -> e = 0 -> constant outputs
    if (rank == 0) {
        const float cs = tanhf(d_ms[b] + bs[0]);
        const float ce = tanhf(d_me[b] + be[0]);
        for (int i = len + tid; i < T; i += 512) {
            out[b*T + i]       = cs;
            out[B*T + b*T + i] = ce;
        }
    }
    cluster_sync_all();                        // no CTA exits with peer DSMEM in flight
}

// ---------------- entry point ----------------
extern "C" void kernel_launch(void* const* d_in, const int* in_sizes, int n_in,
                              void* d_out, int out_size)
{
    const float* qv   = (const float*)d_in[0];
    const float* fact = (const float*)d_in[1];
    const int*   ilen = (const int*)  d_in[2];
    const float* W1   = (const float*)d_in[3];
    const float* b1   = (const float*)d_in[4];
    const float* W2   = (const float*)d_in[5];
    const float* b2   = (const float*)d_in[6];
    const float* Wr   = (const float*)d_in[7];
    const float* Ur   = (const float*)d_in[8];
    const float* br   = (const float*)d_in[9];
    const float* Wh   = (const float*)d_in[10];
    const float* Uh   = (const float*)d_in[11];
    const float* bh   = (const float*)d_in[12];
    const float* Ws   = (const float*)d_in[13];
    const float* bs   = (const float*)d_in[14];
    const float* We   = (const float*)d_in[15];
    const float* be   = (const float*)d_in[16];
    float* out = (float*)d_out;

    prep_w_kernel<<<256, 256>>>(W1);
    prep_u16_kernel<<<256, 256>>>(Ur, Uh);
    prep_batch_kernel<<<64, 256>>>(qv, W1, b1, Ws, We);
    gemm_xrh_kernel<<<dim3(512, 8), 256>>>(fact, Wr, Wh, br, bh);
    gemm_att_kernel<<<dim3(512, 4), 256>>>(fact, qv, W1);
    att_dot_kernel<<<4096, 256>>>(W2, b2);
    softmax_kernel<<<64, 256>>>();
    recurrence_kernel<<<128, 512>>>(ilen, Ws, bs, We, be, out);
}

// round 12
// speedup vs baseline: 1.1679x; 1.1679x over previous
#include <cuda_runtime.h>
#include <cuda_fp16.h>
#include <math.h>
#include <stdint.h>

#define H 256
#define T 512
#define B 64
#define M_TOT (B*T)   // 32768

// ---------------- scratch (static device globals; no allocation) ----------------
__device__ float d_Wfq[H*H];            // W1[3H:4H] + W1[4H:5H]
__device__ float d_Wabs[H*H];           // W1[5H:6H] + W1[6H:7H]
__device__ float d_attpre[B*H];         // q@(W1[H:2H]+W1[2H:3H]) + b1
__device__ float d_ms[B];               // q . Ws[0:H]
__device__ float d_me[B];               // q . We[0:H]
__device__ float d_V[M_TOT*H];          // tanh(feats@W1 + b1)
__device__ float d_att[M_TOT];          // logits
__device__ float d_g[M_TOT];            // softmax gates
__device__ float d_xrh[(size_t)M_TOT*2*H]; // [m][0:256]=x@Wr+br, [256:512]=x@Wh+bh
__device__ __half d_Ur16[H*H];          // fp16 copy of Ur  [k][j]
__device__ __half d_Uh16[H*H];          // fp16 copy of Uh  [k][j]

// ---------------- K0: combine W1 slices ----------------
__global__ __launch_bounds__(256) void prep_w_kernel(const float* __restrict__ W1)
{
    int i = blockIdx.x * 256 + threadIdx.x;           // 65536 total
    d_Wfq[i]  = W1[196608 + i] + W1[262144 + i];      // rows [3H,4H) + [4H,5H)
    d_Wabs[i] = W1[327680 + i] + W1[393216 + i];      // rows [5H,6H) + [6H,7H)
}

// ---------------- K0b: fp16 conversion of Ur/Uh ----------------
__global__ __launch_bounds__(256) void prep_u16_kernel(
    const float* __restrict__ Ur, const float* __restrict__ Uh)
{
    int i = blockIdx.x * 256 + threadIdx.x;           // 65536 total
    d_Ur16[i] = __float2half(Ur[i]);
    d_Uh16[i] = __float2half(Uh[i]);
}

// ---------------- K1: per-batch precompute ----------------
__global__ __launch_bounds__(256) void prep_batch_kernel(
    const float* __restrict__ qv, const float* __restrict__ W1,
    const float* __restrict__ b1, const float* __restrict__ Ws,
    const float* __restrict__ We)
{
    const int b = blockIdx.x, j = threadIdx.x;
    __shared__ float qs[H];
    __shared__ float redS[8], redE[8];
    qs[j] = qv[b*H + j];
    __syncthreads();

    float acc = 0.f;
#pragma unroll 8
    for (int k = 0; k < H; ++k)
        acc += qs[k] * (W1[(H + k)*H + j] + W1[(2*H + k)*H + j]);
    d_attpre[b*H + j] = acc + b1[j];

    float ps = qs[j] * Ws[j];
    float pe = qs[j] * We[j];
#pragma unroll
    for (int off = 16; off; off >>= 1) {
        ps += __shfl_xor_sync(0xffffffffu, ps, off);
        pe += __shfl_xor_sync(0xffffffffu, pe, off);
    }
    if ((j & 31) == 0) { redS[j >> 5] = ps; redE[j >> 5] = pe; }
    __syncthreads();
    if (j == 0) {
        float s = 0.f, se = 0.f;
#pragma unroll
        for (int w = 0; w < 8; ++w) { s += redS[w]; se += redE[w]; }
        d_ms[b] = s;
        d_me[b] = se;
    }
}

// ---------------- K2a: attention GEMM (M=32768, K=768 virtual, N=256) ----------------
__global__ __launch_bounds__(256) void gemm_att_kernel(
    const float* __restrict__ fact, const float* __restrict__ qv,
    const float* __restrict__ W1)
{
    __shared__ float As[16][64];
    __shared__ float Bs[16][64];
    const int tid = threadIdx.x;
    const int m0 = blockIdx.x * 64;        // 64 consecutive rows: same batch (512/64=8)
    const int n0 = blockIdx.y * 64;
    const int b  = m0 >> 9;
    const int tx = tid & 15, ty = tid >> 4;
    const int arow = tid >> 2, akq = (tid & 3) * 4;
    const int bkr = tid >> 4,  bjc = (tid & 15) * 4;

    float acc[4][4] = {};

    for (int sel = 0; sel < 3; ++sel) {
        const float* __restrict__ W = (sel == 0) ? W1 : (sel == 1) ? d_Wfq : d_Wabs;
        for (int kp0 = 0; kp0 < H; kp0 += 16) {
            float4 f4 = *(const float4*)(fact + (m0 + arow)*H + kp0 + akq);
            float4 q4 = *(const float4*)(qv + b*H + kp0 + akq);
            float4 v4;
            if (sel == 0)      v4 = f4;
            else if (sel == 1) { v4.x = f4.x*q4.x; v4.y = f4.y*q4.y;
                                 v4.z = f4.z*q4.z; v4.w = f4.w*q4.w; }
            else               { v4.x = fabsf(f4.x - q4.x); v4.y = fabsf(f4.y - q4.y);
                                 v4.z = fabsf(f4.z - q4.z); v4.w = fabsf(f4.w - q4.w); }
            As[akq + 0][arow] = v4.x;
            As[akq + 1][arow] = v4.y;
            As[akq + 2][arow] = v4.z;
            As[akq + 3][arow] = v4.w;
            *(float4*)&Bs[bkr][bjc] = *(const float4*)(W + (kp0 + bkr)*H + n0 + bjc);
            __syncthreads();
#pragma unroll
            for (int k = 0; k < 16; ++k) {
                float4 a  = *(const float4*)&As[k][ty * 4];
                float4 bb = *(const float4*)&Bs[k][tx * 4];
                acc[0][0] += a.x*bb.x; acc[0][1] += a.x*bb.y; acc[0][2] += a.x*bb.z; acc[0][3] += a.x*bb.w;
                acc[1][0] += a.y*bb.x; acc[1][1] += a.y*bb.y; acc[1][2] += a.y*bb.z; acc[1][3] += a.y*bb.w;
                acc[2][0] += a.z*bb.x; acc[2][1] += a.z*bb.y; acc[2][2] += a.z*bb.z; acc[2][3] += a.z*bb.w;
                acc[3][0] += a.w*bb.x; acc[3][1] += a.w*bb.y; acc[3][2] += a.w*bb.z; acc[3][3] += a.w*bb.w;
            }
            __syncthreads();
        }
    }
#pragma unroll
    for (int i = 0; i < 4; ++i) {
        int m = m0 + ty * 4 + i;
#pragma unroll
        for (int jj = 0; jj < 4; ++jj) {
            int n = n0 + tx * 4 + jj;
            d_V[m*H + n] = tanhf(acc[i][jj] + d_attpre[b*H + n]);
        }
    }
}

// ---------------- K2b: att[m] = V[m] . W2 + b2 ----------------
__global__ __launch_bounds__(256) void att_dot_kernel(
    const float* __restrict__ W2, const float* __restrict__ b2)
{
    const int row  = blockIdx.x * 8 + (threadIdx.x >> 5);
    const int lane = threadIdx.x & 31;
    float s = 0.f;
#pragma unroll
    for (int i = 0; i < 8; ++i) {
        int jj = lane + i * 32;
        s += d_V[row*H + jj] * W2[jj];
    }
#pragma unroll
    for (int off = 16; off; off >>= 1) s += __shfl_xor_sync(0xffffffffu, s, off);
    if (lane == 0) d_att[row] = s + b2[0];
}

// ---------------- K4: softmax over T per batch ----------------
__global__ __launch_bounds__(256) void softmax_kernel()
{
    const int b = blockIdx.x, tid = threadIdx.x;
    __shared__ float sd[256];
    float x0 = d_att[b*T + tid];
    float x1 = d_att[b*T + 256 + tid];
    sd[tid] = fmaxf(x0, x1);
    __syncthreads();
    for (int s = 128; s; s >>= 1) {
        if (tid < s) sd[tid] = fmaxf(sd[tid], sd[tid + s]);
        __syncthreads();
    }
    const float M = sd[0];
    __syncthreads();
    float e0 = expf(x0 - M), e1 = expf(x1 - M);
    sd[tid] = e0 + e1;
    __syncthreads();
    for (int s = 128; s; s >>= 1) {
        if (tid < s) sd[tid] += sd[tid + s];
        __syncthreads();
    }
    const float inv = 1.0f / sd[0];
    d_g[b*T + tid]       = e0 * inv;
    d_g[b*T + 256 + tid] = e1 * inv;
}

// ---------------- K3: XRH GEMM (M=32768, K=256, N=512 = [Wr|Wh]) + bias ----------------
__global__ __launch_bounds__(256) void gemm_xrh_kernel(
    const float* __restrict__ fact, const float* __restrict__ Wr,
    const float* __restrict__ Wh,   const float* __restrict__ br,
    const float* __restrict__ bh)
{
    __shared__ float As[16][64];
    __shared__ float Bs[16][64];
    const int tid = threadIdx.x;
    const int m0 = blockIdx.x * 64;
    const int n0 = blockIdx.y * 64;
    const int tx = tid & 15, ty = tid >> 4;
    const int arow = tid >> 2, akq = (tid & 3) * 4;
    const int bkr = tid >> 4,  bjc = (tid & 15) * 4;

    const bool isR = (n0 < H);
    const float* __restrict__ W    = isR ? Wr : Wh;
    const float* __restrict__ bias = isR ? br : bh;
    const int nb = isR ? n0 : n0 - H;

    float acc[4][4] = {};
    for (int k0 = 0; k0 < H; k0 += 16) {
        float4 f4 = *(const float4*)(fact + (m0 + arow)*H + k0 + akq);
        As[akq + 0][arow] = f4.x;
        As[akq + 1][arow] = f4.y;
        As[akq + 2][arow] = f4.z;
        As[akq + 3][arow] = f4.w;
        *(float4*)&Bs[bkr][bjc] = *(const float4*)(W + (k0 + bkr)*H + nb + bjc);
        __syncthreads();
#pragma unroll
        for (int k = 0; k < 16; ++k) {
            float4 a  = *(const float4*)&As[k][ty * 4];
            float4 bb = *(const float4*)&Bs[k][tx * 4];
            acc[0][0] += a.x*bb.x; acc[0][1] += a.x*bb.y; acc[0][2] += a.x*bb.z; acc[0][3] += a.x*bb.w;
            acc[1][0] += a.y*bb.x; acc[1][1] += a.y*bb.y; acc[1][2] += a.y*bb.z; acc[1][3] += a.y*bb.w;
            acc[2][0] += a.z*bb.x; acc[2][1] += a.z*bb.y; acc[2][2] += a.z*bb.z; acc[2][3] += a.z*bb.w;
            acc[3][0] += a.w*bb.x; acc[3][1] += a.w*bb.y; acc[3][2] += a.w*bb.z; acc[3][3] += a.w*bb.w;
        }
        __syncthreads();
    }
#pragma unroll
    for (int i = 0; i < 4; ++i) {
        int m = m0 + ty * 4 + i;
#pragma unroll
        for (int jj = 0; jj < 4; ++jj) {
            int n = n0 + tx * 4 + jj;
            d_xrh[(size_t)m * (2*H) + n] = acc[i][jj] + bias[nb + tx*4 + jj];
        }
    }
}

// ---------------- K5: GRU recurrence — single CTA/batch, Uh in SMEM, Ur via L2 ----------------
// 64 blocks, 512 threads = 16 warps. Warp kg owns k-slice [kg*16, kg*16+16);
// lane jl owns 8 consecutive columns j0 = jl*8 (full 256 cols covered).
// Per k: one 16B load (8 fp16 weights) + 1 smem broadcast + 4 HFMA2.
// Uh (128 KB fp16) lives in dynamic SMEM; Ur streams from global (one shared
// L2-resident copy for all 64 CTAs). h kept in registers of the 256 owner
// threads; h/rh broadcast as duplicated half2 in static smem.
__device__ __forceinline__ void matvec8(
    const __half* __restrict__ Wp,      // &W[k0*H + j0]
    const __half2* __restrict__ src,    // h2 or rh2 (duplicated pairs)
    int k0, float* __restrict__ redrow) // &red[kg][j0]
{
    __half2 aE0, aE1, aE2, aE3, aO0, aO1, aO2, aO3;
    aE0 = aE1 = aE2 = aE3 = aO0 = aO1 = aO2 = aO3 = __float2half2_rn(0.f);
#pragma unroll
    for (int kk = 0; kk < 16; ++kk) {
        uint4 w = *(const uint4*)(Wp + kk * H);
        __half2 hk = src[k0 + kk];
        __half2 w0 = *(__half2*)&w.x, w1 = *(__half2*)&w.y;
        __half2 w2 = *(__half2*)&w.z, w3 = *(__half2*)&w.w;
        if (kk & 1) {
            aO0 = __hfma2(w0, hk, aO0); aO1 = __hfma2(w1, hk, aO1);
            aO2 = __hfma2(w2, hk, aO2); aO3 = __hfma2(w3, hk, aO3);
        } else {
            aE0 = __hfma2(w0, hk, aE0); aE1 = __hfma2(w1, hk, aE1);
            aE2 = __hfma2(w2, hk, aE2); aE3 = __hfma2(w3, hk, aE3);
        }
    }
    float2 e0 = __half22float2(aE0), o0 = __half22float2(aO0);
    float2 e1 = __half22float2(aE1), o1 = __half22float2(aO1);
    float2 e2 = __half22float2(aE2), o2 = __half22float2(aO2);
    float2 e3 = __half22float2(aE3), o3 = __half22float2(aO3);
    *(float4*)redrow       = make_float4(e0.x+o0.x, e0.y+o0.y, e1.x+o1.x, e1.y+o1.y);
    *(float4*)(redrow + 4) = make_float4(e2.x+o2.x, e2.y+o2.y, e3.x+o3.x, e3.y+o3.y);
}

__global__ __launch_bounds__(512) void recurrence_kernel(
    const int* __restrict__ input_len,
    const float* __restrict__ Ws, const float* __restrict__ bs,
    const float* __restrict__ We, const float* __restrict__ be,
    float* __restrict__ out)
{
    extern __shared__ __half Uh_s[];     // [H*H] fp16, 128 KB
    const int b   = blockIdx.x;
    const int tid = threadIdx.x;
    const int kg  = tid >> 5;            // warp = k-group
    const int jl  = tid & 31;
    const int j0  = jl * 8;
    const int k0  = kg * 16;

    __shared__ __half2 h2_s[H];          // duplicated-pair h
    __shared__ __half2 rh2_s[H];         // duplicated-pair r*h
    __shared__ float   red[16][H];       // 16 KB partials
    __shared__ float   redS[8], redE[8];

    // load Uh into smem (128 KB; 16 uint4 per thread)
    {
        const uint4* src = (const uint4*)d_Uh16;
        uint4* dst = (uint4*)Uh_s;
        for (int i = tid; i < H*H/8; i += 512) dst[i] = src[i];
    }
    if (tid < H) h2_s[tid] = __float2half2_rn(0.f);

    const int len = input_len[b];
    const float* __restrict__ xb = d_xrh + (size_t)b * T * (2*H);

    float ws2 = 0.f, we2 = 0.f, xr_c = 0.f, xh_c = 0.f, g_c = 0.f;
    float hj = 0.f, msb = 0.f, meb = 0.f;
    if (tid < H) {
        ws2  = Ws[H + tid];
        we2  = We[H + tid];
        xr_c = xb[tid];
        xh_c = xb[H + tid];
        g_c  = d_g[b*T];
    }
    if (tid == 0) { msb = d_ms[b] + bs[0]; meb = d_me[b] + be[0]; }
    __syncthreads();

    const __half* __restrict__ UrP = d_Ur16 + k0 * H + j0;
    const __half* __restrict__ UhP = Uh_s   + k0 * H + j0;

    float xr_n = 0.f, xh_n = 0.f, g_n = 0.f;
    for (int t = 0; t < len; ++t) {
        // ---- p1: partial h @ Ur (global fp16, L2-shared across CTAs)
        matvec8(UrP, h2_s, k0, &red[kg][j0]);
        __syncthreads();

        // ---- p2: r = sigmoid(xr + sum), rh broadcast
        if (tid < H) {
            float s = xr_c;
#pragma unroll
            for (int g = 0; g < 16; ++g) s += red[g][tid];
            const float r = 1.0f / (1.0f + expf(-s));
            rh2_s[tid] = __float2half2_rn(r * hj);
            const int tn = (t + 1 < T) ? (t + 1) : (T - 1);
            xr_n = xb[tn*(2*H) + tid];
            xh_n = xb[tn*(2*H) + H + tid];
            g_n  = d_g[b*T + tn];
        }
        __syncthreads();

        // ---- p3: partial rh @ Uh (smem)
        matvec8(UhP, rh2_s, k0, &red[kg][j0]);
        __syncthreads();

        // ---- p4: h update + fused output dots
        if (tid < H) {
            float s = xh_c;
#pragma unroll
            for (int g = 0; g < 16; ++g) s += red[g][tid];
            const float hc = tanhf(s);
            const float hn = fmaf(g_c, hc - hj, hj);   // t < len guaranteed
            hj = hn;
            h2_s[tid] = __float2half2_rn(hn);
            float ps = hn * ws2, pe = hn * we2;
#pragma unroll
            for (int off = 16; off; off >>= 1) {
                ps += __shfl_xor_sync(0xffffffffu, ps, off);
                pe += __shfl_xor_sync(0xffffffffu, pe, off);
            }
            if (jl == 0) { redS[tid >> 5] = ps; redE[tid >> 5] = pe; }
            xr_c = xr_n; xh_c = xh_n; g_c = g_n;
        }
        __syncthreads();

        // thread 0 writes outputs while others begin next step
        // (redS/redE next overwritten only after 3 more barriers)
        if (tid == 0) {
            float s = 0.f, se = 0.f;
#pragma unroll
            for (int w = 0; w < 8; ++w) { s += redS[w]; se += redE[w]; }
            out[b*T + t]       = tanhf(msb + s);
            out[B*T + b*T + t] = tanhf(meb + se);
        }
    }

    // tail: t in [len, T): e = 0 -> constant outputs
    {
        const float cs = tanhf(d_ms[b] + bs[0]);
        const float ce = tanhf(d_me[b] + be[0]);
        for (int i = len + tid; i < T; i += 512) {
            out[b*T + i]       = cs;
            out[B*T + b*T + i] = ce;
        }
    }
}

// ---------------- entry point ----------------
extern "C" void kernel_launch(void* const* d_in, const int* in_sizes, int n_in,
                              void* d_out, int out_size)
{
    const float* qv   = (const float*)d_in[0];
    const float* fact = (const float*)d_in[1];
    const int*   ilen = (const int*)  d_in[2];
    const float* W1   = (const float*)d_in[3];
    const float* b1   = (const float*)d_in[4];
    const float* W2   = (const float*)d_in[5];
    const float* b2   = (const float*)d_in[6];
    const float* Wr   = (const float*)d_in[7];
    const float* Ur   = (const float*)d_in[8];
    const float* br   = (const float*)d_in[9];
    const float* Wh   = (const float*)d_in[10];
    const float* Uh   = (const float*)d_in[11];
    const float* bh   = (const float*)d_in[12];
    const float* Ws   = (const float*)d_in[13];
    const float* bs   = (const float*)d_in[14];
    const float* We   = (const float*)d_in[15];
    const float* be   = (const float*)d_in[16];
    float* out = (float*)d_out;

    const int uh_smem = H * H * (int)sizeof(__half);   // 128 KB dynamic
    static int attr_done = 0;
    if (!attr_done) {
        cudaFuncSetAttribute(recurrence_kernel,
                             cudaFuncAttributeMaxDynamicSharedMemorySize, uh_smem);
        attr_done = 1;
    }

    prep_w_kernel<<<256, 256>>>(W1);
    prep_u16_kernel<<<256, 256>>>(Ur, Uh);
    prep_batch_kernel<<<64, 256>>>(qv, W1, b1, Ws, We);
    gemm_xrh_kernel<<<dim3(512, 8), 256>>>(fact, Wr, Wh, br, bh);
    gemm_att_kernel<<<dim3(512, 4), 256>>>(fact, qv, W1);
    att_dot_kernel<<<4096, 256>>>(W2, b2);
    softmax_kernel<<<64, 256>>>();
    recurrence_kernel<<<64, 512, uh_smem>>>(ilen, Ws, bs, We, be, out);
}

// round 13
// speedup vs baseline: 2.1680x; 1.8563x over previous
#include <cuda_runtime.h>
#include <cuda_fp16.h>
#include <math.h>
#include <stdint.h>

#define H 256
#define T 512
#define B 64
#define M_TOT (B*T)   // 32768

// ---------------- scratch (static device globals; no allocation) ----------------
__device__ float d_Wfq[H*H];            // W1[3H:4H] + W1[4H:5H]
__device__ float d_Wabs[H*H];           // W1[5H:6H] + W1[6H:7H]
__device__ float d_attpre[B*H];         // q@(W1[H:2H]+W1[2H:3H]) + b1
__device__ float d_ms[B];               // q . Ws[0:H]
__device__ float d_me[B];               // q . We[0:H]
__device__ float d_V[M_TOT*H];          // tanh(feats@W1 + b1)
__device__ float d_att[M_TOT];          // logits
__device__ float d_g[M_TOT];            // softmax gates
__device__ float d_xrh[(size_t)M_TOT*2*H]; // [m][0:256]=x@Wr+br, [256:512]=x@Wh+bh
__device__ __half d_Ur16[H*H];          // fp16 copy of Ur  [k][j]
__device__ __half d_Uh16[H*H];          // fp16 copy of Uh  [k][j]

// ---------------- K0: combine W1 slices ----------------
__global__ __launch_bounds__(256) void prep_w_kernel(const float* __restrict__ W1)
{
    int i = blockIdx.x * 256 + threadIdx.x;           // 65536 total
    d_Wfq[i]  = W1[196608 + i] + W1[262144 + i];      // rows [3H,4H) + [4H,5H)
    d_Wabs[i] = W1[327680 + i] + W1[393216 + i];      // rows [5H,6H) + [6H,7H)
}

// ---------------- K0b: fp16 conversion of Ur/Uh ----------------
__global__ __launch_bounds__(256) void prep_u16_kernel(
    const float* __restrict__ Ur, const float* __restrict__ Uh)
{
    int i = blockIdx.x * 256 + threadIdx.x;           // 65536 total
    d_Ur16[i] = __float2half(Ur[i]);
    d_Uh16[i] = __float2half(Uh[i]);
}

// ---------------- K1: per-batch precompute ----------------
__global__ __launch_bounds__(256) void prep_batch_kernel(
    const float* __restrict__ qv, const float* __restrict__ W1,
    const float* __restrict__ b1, const float* __restrict__ Ws,
    const float* __restrict__ We)
{
    const int b = blockIdx.x, j = threadIdx.x;
    __shared__ float qs[H];
    __shared__ float redS[8], redE[8];
    qs[j] = qv[b*H + j];
    __syncthreads();

    float acc = 0.f;
#pragma unroll 8
    for (int k = 0; k < H; ++k)
        acc += qs[k] * (W1[(H + k)*H + j] + W1[(2*H + k)*H + j]);
    d_attpre[b*H + j] = acc + b1[j];

    float ps = qs[j] * Ws[j];
    float pe = qs[j] * We[j];
#pragma unroll
    for (int off = 16; off; off >>= 1) {
        ps += __shfl_xor_sync(0xffffffffu, ps, off);
        pe += __shfl_xor_sync(0xffffffffu, pe, off);
    }
    if ((j & 31) == 0) { redS[j >> 5] = ps; redE[j >> 5] = pe; }
    __syncthreads();
    if (j == 0) {
        float s = 0.f, se = 0.f;
#pragma unroll
        for (int w = 0; w < 8; ++w) { s += redS[w]; se += redE[w]; }
        d_ms[b] = s;
        d_me[b] = se;
    }
}

// ---------------- K2a: attention GEMM (M=32768, K=768 virtual, N=256) ----------------
__global__ __launch_bounds__(256) void gemm_att_kernel(
    const float* __restrict__ fact, const float* __restrict__ qv,
    const float* __restrict__ W1)
{
    __shared__ float As[16][64];
    __shared__ float Bs[16][64];
    const int tid = threadIdx.x;
    const int m0 = blockIdx.x * 64;        // 64 consecutive rows: same batch (512/64=8)
    const int n0 = blockIdx.y * 64;
    const int b  = m0 >> 9;
    const int tx = tid & 15, ty = tid >> 4;
    const int arow = tid >> 2, akq = (tid & 3) * 4;
    const int bkr = tid >> 4,  bjc = (tid & 15) * 4;

    float acc[4][4] = {};

    for (int sel = 0; sel < 3; ++sel) {
        const float* __restrict__ W = (sel == 0) ? W1 : (sel == 1) ? d_Wfq : d_Wabs;
        for (int kp0 = 0; kp0 < H; kp0 += 16) {
            float4 f4 = *(const float4*)(fact + (m0 + arow)*H + kp0 + akq);
            float4 q4 = *(const float4*)(qv + b*H + kp0 + akq);
            float4 v4;
            if (sel == 0)      v4 = f4;
            else if (sel == 1) { v4.x = f4.x*q4.x; v4.y = f4.y*q4.y;
                                 v4.z = f4.z*q4.z; v4.w = f4.w*q4.w; }
            else               { v4.x = fabsf(f4.x - q4.x); v4.y = fabsf(f4.y - q4.y);
                                 v4.z = fabsf(f4.z - q4.z); v4.w = fabsf(f4.w - q4.w); }
            As[akq + 0][arow] = v4.x;
            As[akq + 1][arow] = v4.y;
            As[akq + 2][arow] = v4.z;
            As[akq + 3][arow] = v4.w;
            *(float4*)&Bs[bkr][bjc] = *(const float4*)(W + (kp0 + bkr)*H + n0 + bjc);
            __syncthreads();
#pragma unroll
            for (int k = 0; k < 16; ++k) {
                float4 a  = *(const float4*)&As[k][ty * 4];
                float4 bb = *(const float4*)&Bs[k][tx * 4];
                acc[0][0] += a.x*bb.x; acc[0][1] += a.x*bb.y; acc[0][2] += a.x*bb.z; acc[0][3] += a.x*bb.w;
                acc[1][0] += a.y*bb.x; acc[1][1] += a.y*bb.y; acc[1][2] += a.y*bb.z; acc[1][3] += a.y*bb.w;
                acc[2][0] += a.z*bb.x; acc[2][1] += a.z*bb.y; acc[2][2] += a.z*bb.z; acc[2][3] += a.z*bb.w;
                acc[3][0] += a.w*bb.x; acc[3][1] += a.w*bb.y; acc[3][2] += a.w*bb.z; acc[3][3] += a.w*bb.w;
            }
            __syncthreads();
        }
    }
#pragma unroll
    for (int i = 0; i < 4; ++i) {
        int m = m0 + ty * 4 + i;
#pragma unroll
        for (int jj = 0; jj < 4; ++jj) {
            int n = n0 + tx * 4 + jj;
            d_V[m*H + n] = tanhf(acc[i][jj] + d_attpre[b*H + n]);
        }
    }
}

// ---------------- K2b: att[m] = V[m] . W2 + b2 ----------------
__global__ __launch_bounds__(256) void att_dot_kernel(
    const float* __restrict__ W2, const float* __restrict__ b2)
{
    const int row  = blockIdx.x * 8 + (threadIdx.x >> 5);
    const int lane = threadIdx.x & 31;
    float s = 0.f;
#pragma unroll
    for (int i = 0; i < 8; ++i) {
        int jj = lane + i * 32;
        s += d_V[row*H + jj] * W2[jj];
    }
#pragma unroll
    for (int off = 16; off; off >>= 1) s += __shfl_xor_sync(0xffffffffu, s, off);
    if (lane == 0) d_att[row] = s + b2[0];
}

// ---------------- K4: softmax over T per batch ----------------
__global__ __launch_bounds__(256) void softmax_kernel()
{
    const int b = blockIdx.x, tid = threadIdx.x;
    __shared__ float sd[256];
    float x0 = d_att[b*T + tid];
    float x1 = d_att[b*T + 256 + tid];
    sd[tid] = fmaxf(x0, x1);
    __syncthreads();
    for (int s = 128; s; s >>= 1) {
        if (tid < s) sd[tid] = fmaxf(sd[tid], sd[tid + s]);
        __syncthreads();
    }
    const float M = sd[0];
    __syncthreads();
    float e0 = expf(x0 - M), e1 = expf(x1 - M);
    sd[tid] = e0 + e1;
    __syncthreads();
    for (int s = 128; s; s >>= 1) {
        if (tid < s) sd[tid] += sd[tid + s];
        __syncthreads();
    }
    const float inv = 1.0f / sd[0];
    d_g[b*T + tid]       = e0 * inv;
    d_g[b*T + 256 + tid] = e1 * inv;
}

// ---------------- K3: XRH GEMM (M=32768, K=256, N=512 = [Wr|Wh]) + bias ----------------
__global__ __launch_bounds__(256) void gemm_xrh_kernel(
    const float* __restrict__ fact, const float* __restrict__ Wr,
    const float* __restrict__ Wh,   const float* __restrict__ br,
    const float* __restrict__ bh)
{
    __shared__ float As[16][64];
    __shared__ float Bs[16][64];
    const int tid = threadIdx.x;
    const int m0 = blockIdx.x * 64;
    const int n0 = blockIdx.y * 64;
    const int tx = tid & 15, ty = tid >> 4;
    const int arow = tid >> 2, akq = (tid & 3) * 4;
    const int bkr = tid >> 4,  bjc = (tid & 15) * 4;

    const bool isR = (n0 < H);
    const float* __restrict__ W    = isR ? Wr : Wh;
    const float* __restrict__ bias = isR ? br : bh;
    const int nb = isR ? n0 : n0 - H;

    float acc[4][4] = {};
    for (int k0 = 0; k0 < H; k0 += 16) {
        float4 f4 = *(const float4*)(fact + (m0 + arow)*H + k0 + akq);
        As[akq + 0][arow] = f4.x;
        As[akq + 1][arow] = f4.y;
        As[akq + 2][arow] = f4.z;
        As[akq + 3][arow] = f4.w;
        *(float4*)&Bs[bkr][bjc] = *(const float4*)(W + (k0 + bkr)*H + nb + bjc);
        __syncthreads();
#pragma unroll
        for (int k = 0; k < 16; ++k) {
            float4 a  = *(const float4*)&As[k][ty * 4];
            float4 bb = *(const float4*)&Bs[k][tx * 4];
            acc[0][0] += a.x*bb.x; acc[0][1] += a.x*bb.y; acc[0][2] += a.x*bb.z; acc[0][3] += a.x*bb.w;
            acc[1][0] += a.y*bb.x; acc[1][1] += a.y*bb.y; acc[1][2] += a.y*bb.z; acc[1][3] += a.y*bb.w;
            acc[2][0] += a.z*bb.x; acc[2][1] += a.z*bb.y; acc[2][2] += a.z*bb.z; acc[2][3] += a.z*bb.w;
            acc[3][0] += a.w*bb.x; acc[3][1] += a.w*bb.y; acc[3][2] += a.w*bb.z; acc[3][3] += a.w*bb.w;
        }
        __syncthreads();
    }
#pragma unroll
    for (int i = 0; i < 4; ++i) {
        int m = m0 + ty * 4 + i;
#pragma unroll
        for (int jj = 0; jj < 4; ++jj) {
            int n = n0 + tx * 4 + jj;
            d_xrh[(size_t)m * (2*H) + n] = acc[i][jj] + bias[nb + tx*4 + jj];
        }
    }
}

// ---------------- K5: GRU recurrence — Ur in REGISTERS, Uh in SMEM ----------------
// 64 blocks, 512 threads = 16 warps. Warp kg owns k-slice [kg*16, kg*16+16);
// lane jl owns 8 consecutive columns j0 = jl*8.
// Ur slice (16 x uint4 = 64 regs/thread) loaded ONCE: p1 has zero load traffic.
// Uh (128 KB fp16) in dynamic SMEM. h/rh broadcast as duplicated half2 in smem.
__device__ __forceinline__ void drain8(
    __half2 aE0, __half2 aE1, __half2 aE2, __half2 aE3,
    __half2 aO0, __half2 aO1, __half2 aO2, __half2 aO3,
    float* __restrict__ redrow)
{
    float2 e0 = __half22float2(aE0), o0 = __half22float2(aO0);
    float2 e1 = __half22float2(aE1), o1 = __half22float2(aO1);
    float2 e2 = __half22float2(aE2), o2 = __half22float2(aO2);
    float2 e3 = __half22float2(aE3), o3 = __half22float2(aO3);
    *(float4*)redrow       = make_float4(e0.x+o0.x, e0.y+o0.y, e1.x+o1.x, e1.y+o1.y);
    *(float4*)(redrow + 4) = make_float4(e2.x+o2.x, e2.y+o2.y, e3.x+o3.x, e3.y+o3.y);
}

__global__ __launch_bounds__(512) void recurrence_kernel(
    const int* __restrict__ input_len,
    const float* __restrict__ Ws, const float* __restrict__ bs,
    const float* __restrict__ We, const float* __restrict__ be,
    float* __restrict__ out)
{
    extern __shared__ __half Uh_s[];     // [H*H] fp16, 128 KB
    const int b   = blockIdx.x;
    const int tid = threadIdx.x;
    const int kg  = tid >> 5;            // warp = k-group
    const int jl  = tid & 31;
    const int j0  = jl * 8;
    const int k0  = kg * 16;

    __shared__ __half2 h2_s[H];          // duplicated-pair h
    __shared__ __half2 rh2_s[H];         // duplicated-pair r*h
    __shared__ float   red[16][H];       // 16 KB partials
    __shared__ float   redS[8], redE[8];

    // Ur slice permanently in registers: wr[kk] = Ur[k0+kk][j0..j0+7]
    uint4 wr[16];
#pragma unroll
    for (int kk = 0; kk < 16; ++kk)
        wr[kk] = *(const uint4*)(d_Ur16 + (k0 + kk) * H + j0);

    // load Uh into smem (128 KB; 16 uint4 per thread)
    {
        const uint4* src = (const uint4*)d_Uh16;
        uint4* dst = (uint4*)Uh_s;
        for (int i = tid; i < H*H/8; i += 512) dst[i] = src[i];
    }
    if (tid < H) h2_s[tid] = __float2half2_rn(0.f);

    const int len = input_len[b];
    const float* __restrict__ xb = d_xrh + (size_t)b * T * (2*H);

    float ws2 = 0.f, we2 = 0.f, xr_c = 0.f, xh_c = 0.f, g_c = 0.f;
    float hj = 0.f, msb = 0.f, meb = 0.f;
    if (tid < H) {
        ws2  = Ws[H + tid];
        we2  = We[H + tid];
        xr_c = xb[tid];
        xh_c = xb[H + tid];
        g_c  = d_g[b*T];
    }
    if (tid == 0) { msb = d_ms[b] + bs[0]; meb = d_me[b] + be[0]; }
    __syncthreads();

    const __half* __restrict__ UhP = Uh_s + k0 * H + j0;
    const __half2 hz = __float2half2_rn(0.f);

    float xr_n = 0.f, xh_n = 0.f, g_n = 0.f;
    for (int t = 0; t < len; ++t) {
        // ---- p1: partial h @ Ur — weights from registers, zero load traffic
        {
            __half2 aE0 = hz, aE1 = hz, aE2 = hz, aE3 = hz;
            __half2 aO0 = hz, aO1 = hz, aO2 = hz, aO3 = hz;
#pragma unroll
            for (int kk = 0; kk < 16; ++kk) {
                const uint4 w = wr[kk];
                const __half2 hk = h2_s[k0 + kk];
                __half2 w0 = *(const __half2*)&w.x, w1 = *(const __half2*)&w.y;
                __half2 w2 = *(const __half2*)&w.z, w3 = *(const __half2*)&w.w;
                if (kk & 1) {
                    aO0 = __hfma2(w0, hk, aO0); aO1 = __hfma2(w1, hk, aO1);
                    aO2 = __hfma2(w2, hk, aO2); aO3 = __hfma2(w3, hk, aO3);
                } else {
                    aE0 = __hfma2(w0, hk, aE0); aE1 = __hfma2(w1, hk, aE1);
                    aE2 = __hfma2(w2, hk, aE2); aE3 = __hfma2(w3, hk, aE3);
                }
            }
            drain8(aE0, aE1, aE2, aE3, aO0, aO1, aO2, aO3, &red[kg][j0]);
        }
        __syncthreads();

        // ---- p2: r = sigmoid(xr + sum), rh broadcast
        if (tid < H) {
            float s = xr_c;
#pragma unroll
            for (int g = 0; g < 16; ++g) s += red[g][tid];
            const float r = 1.0f / (1.0f + expf(-s));
            rh2_s[tid] = __float2half2_rn(r * hj);
            const int tn = (t + 1 < T) ? (t + 1) : (T - 1);
            xr_n = xb[tn*(2*H) + tid];
            xh_n = xb[tn*(2*H) + H + tid];
            g_n  = d_g[b*T + tn];
        }
        __syncthreads();

        // ---- p3: partial rh @ Uh (smem weights)
        {
            __half2 aE0 = hz, aE1 = hz, aE2 = hz, aE3 = hz;
            __half2 aO0 = hz, aO1 = hz, aO2 = hz, aO3 = hz;
#pragma unroll
            for (int kk = 0; kk < 16; ++kk) {
                const uint4 w = *(const uint4*)(UhP + kk * H);
                const __half2 hk = rh2_s[k0 + kk];
                __half2 w0 = *(const __half2*)&w.x, w1 = *(const __half2*)&w.y;
                __half2 w2 = *(const __half2*)&w.z, w3 = *(const __half2*)&w.w;
                if (kk & 1) {
                    aO0 = __hfma2(w0, hk, aO0); aO1 = __hfma2(w1, hk, aO1);
                    aO2 = __hfma2(w2, hk, aO2); aO3 = __hfma2(w3, hk, aO3);
                } else {
                    aE0 = __hfma2(w0, hk, aE0); aE1 = __hfma2(w1, hk, aE1);
                    aE2 = __hfma2(w2, hk, aE2); aE3 = __hfma2(w3, hk, aE3);
                }
            }
            drain8(aE0, aE1, aE2, aE3, aO0, aO1, aO2, aO3, &red[kg][j0]);
        }
        __syncthreads();

        // ---- p4: h update + fused output dots
        if (tid < H) {
            float s = xh_c;
#pragma unroll
            for (int g = 0; g < 16; ++g) s += red[g][tid];
            const float hc = tanhf(s);
            const float hn = fmaf(g_c, hc - hj, hj);   // t < len guaranteed
            hj = hn;
            h2_s[tid] = __float2half2_rn(hn);
            float ps = hn * ws2, pe = hn * we2;
#pragma unroll
            for (int off = 16; off; off >>= 1) {
                ps += __shfl_xor_sync(0xffffffffu, ps, off);
                pe += __shfl_xor_sync(0xffffffffu, pe, off);
            }
            if (jl == 0) { redS[tid >> 5] = ps; redE[tid >> 5] = pe; }
            xr_c = xr_n; xh_c = xh_n; g_c = g_n;
        }
        __syncthreads();

        // thread 0 writes outputs while others begin next step
        if (tid == 0) {
            float s = 0.f, se = 0.f;
#pragma unroll
            for (int w = 0; w < 8; ++w) { s += redS[w]; se += redE[w]; }
            out[b*T + t]       = tanhf(msb + s);
            out[B*T + b*T + t] = tanhf(meb + se);
        }
    }

    // tail: t in [len, T): e = 0 -> constant outputs
    {
        const float cs = tanhf(d_ms[b] + bs[0]);
        const float ce = tanhf(d_me[b] + be[0]);
        for (int i = len + tid; i < T; i += 512) {
            out[b*T + i]       = cs;
            out[B*T + b*T + i] = ce;
        }
    }
}

// ---------------- entry point ----------------
extern "C" void kernel_launch(void* const* d_in, const int* in_sizes, int n_in,
                              void* d_out, int out_size)
{
    const float* qv   = (const float*)d_in[0];
    const float* fact = (const float*)d_in[1];
    const int*   ilen = (const int*)  d_in[2];
    const float* W1   = (const float*)d_in[3];
    const float* b1   = (const float*)d_in[4];
    const float* W2   = (const float*)d_in[5];
    const float* b2   = (const float*)d_in[6];
    const float* Wr   = (const float*)d_in[7];
    const float* Ur   = (const float*)d_in[8];
    const float* br   = (const float*)d_in[9];
    const float* Wh   = (const float*)d_in[10];
    const float* Uh   = (const float*)d_in[11];
    const float* bh   = (const float*)d_in[12];
    const float* Ws   = (const float*)d_in[13];
    const float* bs   = (const float*)d_in[14];
    const float* We   = (const float*)d_in[15];
    const float* be   = (const float*)d_in[16];
    float* out = (float*)d_out;

    const int uh_smem = H * H * (int)sizeof(__half);   // 128 KB dynamic
    static int attr_done = 0;
    if (!attr_done) {
        cudaFuncSetAttribute(recurrence_kernel,
                             cudaFuncAttributeMaxDynamicSharedMemorySize, uh_smem);
        attr_done = 1;
    }

    prep_w_kernel<<<256, 256>>>(W1);
    prep_u16_kernel<<<256, 256>>>(Ur, Uh);
    prep_batch_kernel<<<64, 256>>>(qv, W1, b1, Ws, We);
    gemm_xrh_kernel<<<dim3(512, 8), 256>>>(fact, Wr, Wh, br, bh);
    gemm_att_kernel<<<dim3(512, 4), 256>>>(fact, qv, W1);
    att_dot_kernel<<<4096, 256>>>(W2, b2);
    softmax_kernel<<<64, 256>>>();
    recurrence_kernel<<<64, 512, uh_smem>>>(ilen, Ws, bs, We, be, out);
}

// round 14
// speedup vs baseline: 2.2805x; 1.0519x over previous
#include <cuda_runtime.h>
#include <cuda_fp16.h>
#include <math.h>
#include <stdint.h>

#define H 256
#define T 512
#define B 64
#define M_TOT (B*T)   // 32768

// ---------------- scratch (static device globals; no allocation) ----------------
__device__ float d_attpre[B*H];         // q@(W1[H:2H]+W1[2H:3H]) + b1
__device__ float d_ms[B];               // q . Ws[0:H]
__device__ float d_me[B];               // q . We[0:H]
__device__ float d_att[M_TOT];          // logits
__device__ float d_g[M_TOT];            // softmax gates
__device__ float d_xrh[(size_t)M_TOT*2*H]; // [m][0:256]=x@Wr+br, [256:512]=x@Wh+bh
__device__ __align__(16) __half d_Ur16[H*H];   // fp16 Ur  [k][j]
__device__ __align__(16) __half d_Uh16[H*H];   // fp16 Uh  [k][j]
__device__ __align__(16) __half d_Wr16[H*H];   // fp16 Wr
__device__ __align__(16) __half d_Wh16[H*H];   // fp16 Wh
__device__ __align__(16) __half d_W1f16[H*H];  // fp16 W1 rows [0,H)
__device__ __align__(16) __half d_Wfq16[H*H];  // fp16 (W1[3H:4H]+W1[4H:5H])
__device__ __align__(16) __half d_Wabs16[H*H]; // fp16 (W1[5H:6H]+W1[6H:7H])
__device__ __align__(16) __half d_V16[M_TOT*H]; // tanh(feats@W1+b1) in fp16

// ---------------- K0: fp16 weight prep (W1 slices) ----------------
__global__ __launch_bounds__(256) void prep_w_kernel(const float* __restrict__ W1)
{
    int i = blockIdx.x * 256 + threadIdx.x;           // 65536 total
    d_W1f16[i]  = __float2half(W1[i]);                             // rows [0,H)
    d_Wfq16[i]  = __float2half(W1[196608 + i] + W1[262144 + i]);   // [3H,4H)+[4H,5H)
    d_Wabs16[i] = __float2half(W1[327680 + i] + W1[393216 + i]);   // [5H,6H)+[6H,7H)
}

// ---------------- K0b: fp16 conversion of Ur/Uh/Wr/Wh ----------------
__global__ __launch_bounds__(256) void prep_u16_kernel(
    const float* __restrict__ Ur, const float* __restrict__ Uh,
    const float* __restrict__ Wr, const float* __restrict__ Wh)
{
    int i = blockIdx.x * 256 + threadIdx.x;           // 65536 total
    d_Ur16[i] = __float2half(Ur[i]);
    d_Uh16[i] = __float2half(Uh[i]);
    d_Wr16[i] = __float2half(Wr[i]);
    d_Wh16[i] = __float2half(Wh[i]);
}

// ---------------- K1: per-batch precompute (fp32, exact) ----------------
__global__ __launch_bounds__(256) void prep_batch_kernel(
    const float* __restrict__ qv, const float* __restrict__ W1,
    const float* __restrict__ b1, const float* __restrict__ Ws,
    const float* __restrict__ We)
{
    const int b = blockIdx.x, j = threadIdx.x;
    __shared__ float qs[H];
    __shared__ float redS[8], redE[8];
    qs[j] = qv[b*H + j];
    __syncthreads();

    float acc = 0.f;
#pragma unroll 8
    for (int k = 0; k < H; ++k)
        acc += qs[k] * (W1[(H + k)*H + j] + W1[(2*H + k)*H + j]);
    d_attpre[b*H + j] = acc + b1[j];

    float ps = qs[j] * Ws[j];
    float pe = qs[j] * We[j];
#pragma unroll
    for (int off = 16; off; off >>= 1) {
        ps += __shfl_xor_sync(0xffffffffu, ps, off);
        pe += __shfl_xor_sync(0xffffffffu, pe, off);
    }
    if ((j & 31) == 0) { redS[j >> 5] = ps; redE[j >> 5] = pe; }
    __syncthreads();
    if (j == 0) {
        float s = 0.f, se = 0.f;
#pragma unroll
        for (int w = 0; w < 8; ++w) { s += redS[w]; se += redE[w]; }
        d_ms[b] = s;
        d_me[b] = se;
    }
}

// ---------------- K2a: attention GEMM, fp16 HFMA2 (M=32768, K=768 virt, N=256) ----------------
__global__ __launch_bounds__(256) void gemm_att16_kernel(
    const float* __restrict__ fact, const float* __restrict__ qv)
{
    __shared__ __half As[32][64];
    __shared__ __half Bs[32][64];
    const int tid = threadIdx.x;
    const int m0 = blockIdx.x * 64;        // 64 rows: same batch (512/64=8)
    const int n0 = blockIdx.y * 64;
    const int b  = m0 >> 9;
    const int tx = tid & 15, ty = tid >> 4;
    const int arow = tid >> 2, akq = (tid & 3) * 8;   // A: 4 thr/row, 8 k each
    const int brow = tid >> 3, bjc = (tid & 7) * 8;   // B: 8 thr/row, 8 n each

    float acc[4][4] = {};

    for (int sel = 0; sel < 3; ++sel) {
        const __half* __restrict__ W16 =
            (sel == 0) ? d_W1f16 : (sel == 1) ? d_Wfq16 : d_Wabs16;
        for (int kp0 = 0; kp0 < H; kp0 += 32) {
            // ---- A tile fill (transform fp32 -> fp16)
            const float* fp = fact + (m0 + arow)*H + kp0 + akq;
            const float* qp = qv + b*H + kp0 + akq;
            float4 fa = *(const float4*)fp,       fb = *(const float4*)(fp + 4);
            float4 qa = *(const float4*)qp,       qb = *(const float4*)(qp + 4);
            float v[8];
            if (sel == 0) {
                v[0]=fa.x; v[1]=fa.y; v[2]=fa.z; v[3]=fa.w;
                v[4]=fb.x; v[5]=fb.y; v[6]=fb.z; v[7]=fb.w;
            } else if (sel == 1) {
                v[0]=fa.x*qa.x; v[1]=fa.y*qa.y; v[2]=fa.z*qa.z; v[3]=fa.w*qa.w;
                v[4]=fb.x*qb.x; v[5]=fb.y*qb.y; v[6]=fb.z*qb.z; v[7]=fb.w*qb.w;
            } else {
                v[0]=fabsf(fa.x-qa.x); v[1]=fabsf(fa.y-qa.y);
                v[2]=fabsf(fa.z-qa.z); v[3]=fabsf(fa.w-qa.w);
                v[4]=fabsf(fb.x-qb.x); v[5]=fabsf(fb.y-qb.y);
                v[6]=fabsf(fb.z-qb.z); v[7]=fabsf(fb.w-qb.w);
            }
#pragma unroll
            for (int i = 0; i < 8; ++i)
                As[akq + i][arow] = __float2half(v[i]);
            // ---- B tile fill (fp16, vectorized)
            *(uint4*)&Bs[brow][bjc] = *(const uint4*)(W16 + (kp0 + brow)*H + n0 + bjc);
            __syncthreads();

            // ---- inner product over 32 k, half2 even/odd chains
            __half2 aE[4][2], aO[4][2];
            const __half2 hz = __float2half2_rn(0.f);
#pragma unroll
            for (int i = 0; i < 4; ++i) { aE[i][0]=hz; aE[i][1]=hz; aO[i][0]=hz; aO[i][1]=hz; }
#pragma unroll
            for (int k = 0; k < 32; ++k) {
                uint2 a2 = *(const uint2*)&As[k][ty * 4];
                __half2 a01 = *(__half2*)&a2.x, a23 = *(__half2*)&a2.y;
                __half2 ha0 = __low2half2(a01), ha1 = __high2half2(a01);
                __half2 ha2 = __low2half2(a23), ha3 = __high2half2(a23);
                uint2 b2v = *(const uint2*)&Bs[k][tx * 4];
                __half2 b01 = *(__half2*)&b2v.x, b23 = *(__half2*)&b2v.y;
                if (k & 1) {
                    aO[0][0]=__hfma2(ha0,b01,aO[0][0]); aO[0][1]=__hfma2(ha0,b23,aO[0][1]);
                    aO[1][0]=__hfma2(ha1,b01,aO[1][0]); aO[1][1]=__hfma2(ha1,b23,aO[1][1]);
                    aO[2][0]=__hfma2(ha2,b01,aO[2][0]); aO[2][1]=__hfma2(ha2,b23,aO[2][1]);
                    aO[3][0]=__hfma2(ha3,b01,aO[3][0]); aO[3][1]=__hfma2(ha3,b23,aO[3][1]);
                } else {
                    aE[0][0]=__hfma2(ha0,b01,aE[0][0]); aE[0][1]=__hfma2(ha0,b23,aE[0][1]);
                    aE[1][0]=__hfma2(ha1,b01,aE[1][0]); aE[1][1]=__hfma2(ha1,b23,aE[1][1]);
                    aE[2][0]=__hfma2(ha2,b01,aE[2][0]); aE[2][1]=__hfma2(ha2,b23,aE[2][1]);
                    aE[3][0]=__hfma2(ha3,b01,aE[3][0]); aE[3][1]=__hfma2(ha3,b23,aE[3][1]);
                }
            }
            __syncthreads();
            // ---- drain to fp32 (per 32-k tile)
#pragma unroll
            for (int i = 0; i < 4; ++i) {
#pragma unroll
                for (int j2 = 0; j2 < 2; ++j2) {
                    float2 e = __half22float2(aE[i][j2]);
                    float2 o = __half22float2(aO[i][j2]);
                    acc[i][2*j2]   += e.x + o.x;
                    acc[i][2*j2+1] += e.y + o.y;
                }
            }
        }
    }
#pragma unroll
    for (int i = 0; i < 4; ++i) {
        int m = m0 + ty * 4 + i;
#pragma unroll
        for (int jj = 0; jj < 4; ++jj) {
            int n = n0 + tx * 4 + jj;
            d_V16[m*H + n] = __float2half(tanhf(acc[i][jj] + d_attpre[b*H + n]));
        }
    }
}

// ---------------- K2b: att[m] = V16[m] . W2 + b2 ----------------
__global__ __launch_bounds__(256) void att_dot_kernel(
    const float* __restrict__ W2, const float* __restrict__ b2)
{
    const int row  = blockIdx.x * 8 + (threadIdx.x >> 5);
    const int lane = threadIdx.x & 31;
    uint4 v = *(const uint4*)(d_V16 + row*H + lane*8);
    const __half2* vh = (const __half2*)&v;
    float s = 0.f;
#pragma unroll
    for (int i = 0; i < 4; ++i) {
        float2 f = __half22float2(vh[i]);
        s += f.x * W2[lane*8 + 2*i] + f.y * W2[lane*8 + 2*i + 1];
    }
#pragma unroll
    for (int off = 16; off; off >>= 1) s += __shfl_xor_sync(0xffffffffu, s, off);
    if (lane == 0) d_att[row] = s + b2[0];
}

// ---------------- K4: softmax over T per batch ----------------
__global__ __launch_bounds__(256) void softmax_kernel()
{
    const int b = blockIdx.x, tid = threadIdx.x;
    __shared__ float sd[256];
    float x0 = d_att[b*T + tid];
    float x1 = d_att[b*T + 256 + tid];
    sd[tid] = fmaxf(x0, x1);
    __syncthreads();
    for (int s = 128; s; s >>= 1) {
        if (tid < s) sd[tid] = fmaxf(sd[tid], sd[tid + s]);
        __syncthreads();
    }
    const float M = sd[0];
    __syncthreads();
    float e0 = expf(x0 - M), e1 = expf(x1 - M);
    sd[tid] = e0 + e1;
    __syncthreads();
    for (int s = 128; s; s >>= 1) {
        if (tid < s) sd[tid] += sd[tid + s];
        __syncthreads();
    }
    const float inv = 1.0f / sd[0];
    d_g[b*T + tid]       = e0 * inv;
    d_g[b*T + 256 + tid] = e1 * inv;
}

// ---------------- K3: XRH GEMM fp16 (M=32768, K=256, N=512 = [Wr|Wh]) + bias ----------------
__global__ __launch_bounds__(256) void gemm_xrh16_kernel(
    const float* __restrict__ fact,
    const float* __restrict__ br, const float* __restrict__ bh)
{
    __shared__ __half As[32][64];
    __shared__ __half Bs[32][64];
    const int tid = threadIdx.x;
    const int m0 = blockIdx.x * 64;
    const int n0 = blockIdx.y * 64;
    const int tx = tid & 15, ty = tid >> 4;
    const int arow = tid >> 2, akq = (tid & 3) * 8;
    const int brow = tid >> 3, bjc = (tid & 7) * 8;

    const bool isR = (n0 < H);
    const __half* __restrict__ W16  = isR ? d_Wr16 : d_Wh16;
    const float*  __restrict__ bias = isR ? br : bh;
    const int nb = isR ? n0 : n0 - H;

    float acc[4][4] = {};
    for (int kp0 = 0; kp0 < H; kp0 += 32) {
        const float* fp = fact + (m0 + arow)*H + kp0 + akq;
        float4 fa = *(const float4*)fp, fb = *(const float4*)(fp + 4);
        As[akq + 0][arow] = __float2half(fa.x);
        As[akq + 1][arow] = __float2half(fa.y);
        As[akq + 2][arow] = __float2half(fa.z);
        As[akq + 3][arow] = __float2half(fa.w);
        As[akq + 4][arow] = __float2half(fb.x);
        As[akq + 5][arow] = __float2half(fb.y);
        As[akq + 6][arow] = __float2half(fb.z);
        As[akq + 7][arow] = __float2half(fb.w);
        *(uint4*)&Bs[brow][bjc] = *(const uint4*)(W16 + (kp0 + brow)*H + nb + bjc);
        __syncthreads();

        __half2 aE[4][2], aO[4][2];
        const __half2 hz = __float2half2_rn(0.f);
#pragma unroll
        for (int i = 0; i < 4; ++i) { aE[i][0]=hz; aE[i][1]=hz; aO[i][0]=hz; aO[i][1]=hz; }
#pragma unroll
        for (int k = 0; k < 32; ++k) {
            uint2 a2 = *(const uint2*)&As[k][ty * 4];
            __half2 a01 = *(__half2*)&a2.x, a23 = *(__half2*)&a2.y;
            __half2 ha0 = __low2half2(a01), ha1 = __high2half2(a01);
            __half2 ha2 = __low2half2(a23), ha3 = __high2half2(a23);
            uint2 b2v = *(const uint2*)&Bs[k][tx * 4];
            __half2 b01 = *(__half2*)&b2v.x, b23 = *(__half2*)&b2v.y;
            if (k & 1) {
                aO[0][0]=__hfma2(ha0,b01,aO[0][0]); aO[0][1]=__hfma2(ha0,b23,aO[0][1]);
                aO[1][0]=__hfma2(ha1,b01,aO[1][0]); aO[1][1]=__hfma2(ha1,b23,aO[1][1]);
                aO[2][0]=__hfma2(ha2,b01,aO[2][0]); aO[2][1]=__hfma2(ha2,b23,aO[2][1]);
                aO[3][0]=__hfma2(ha3,b01,aO[3][0]); aO[3][1]=__hfma2(ha3,b23,aO[3][1]);
            } else {
                aE[0][0]=__hfma2(ha0,b01,aE[0][0]); aE[0][1]=__hfma2(ha0,b23,aE[0][1]);
                aE[1][0]=__hfma2(ha1,b01,aE[1][0]); aE[1][1]=__hfma2(ha1,b23,aE[1][1]);
                aE[2][0]=__hfma2(ha2,b01,aE[2][0]); aE[2][1]=__hfma2(ha2,b23,aE[2][1]);
                aE[3][0]=__hfma2(ha3,b01,aE[3][0]); aE[3][1]=__hfma2(ha3,b23,aE[3][1]);
            }
        }
        __syncthreads();
#pragma unroll
        for (int i = 0; i < 4; ++i) {
#pragma unroll
            for (int j2 = 0; j2 < 2; ++j2) {
                float2 e = __half22float2(aE[i][j2]);
                float2 o = __half22float2(aO[i][j2]);
                acc[i][2*j2]   += e.x + o.x;
                acc[i][2*j2+1] += e.y + o.y;
            }
        }
    }
#pragma unroll
    for (int i = 0; i < 4; ++i) {
        int m = m0 + ty * 4 + i;
#pragma unroll
        for (int jj = 0; jj < 4; ++jj) {
            int n = n0 + tx * 4 + jj;
            d_xrh[(size_t)m * (2*H) + n] = acc[i][jj] + bias[nb + tx*4 + jj];
        }
    }
}

// ---------------- K5: GRU recurrence — Ur in REGISTERS, Uh in SMEM (unchanged) ----------------
__device__ __forceinline__ void drain8(
    __half2 aE0, __half2 aE1, __half2 aE2, __half2 aE3,
    __half2 aO0, __half2 aO1, __half2 aO2, __half2 aO3,
    float* __restrict__ redrow)
{
    float2 e0 = __half22float2(aE0), o0 = __half22float2(aO0);
    float2 e1 = __half22float2(aE1), o1 = __half22float2(aO1);
    float2 e2 = __half22float2(aE2), o2 = __half22float2(aO2);
    float2 e3 = __half22float2(aE3), o3 = __half22float2(aO3);
    *(float4*)redrow       = make_float4(e0.x+o0.x, e0.y+o0.y, e1.x+o1.x, e1.y+o1.y);
    *(float4*)(redrow + 4) = make_float4(e2.x+o2.x, e2.y+o2.y, e3.x+o3.x, e3.y+o3.y);
}

__global__ __launch_bounds__(512) void recurrence_kernel(
    const int* __restrict__ input_len,
    const float* __restrict__ Ws, const float* __restrict__ bs,
    const float* __restrict__ We, const float* __restrict__ be,
    float* __restrict__ out)
{
    extern __shared__ __half Uh_s[];     // [H*H] fp16, 128 KB
    const int b   = blockIdx.x;
    const int tid = threadIdx.x;
    const int kg  = tid >> 5;            // warp = k-group
    const int jl  = tid & 31;
    const int j0  = jl * 8;
    const int k0  = kg * 16;

    __shared__ __half2 h2_s[H];          // duplicated-pair h
    __shared__ __half2 rh2_s[H];         // duplicated-pair r*h
    __shared__ float   red[16][H];       // 16 KB partials
    __shared__ float   redS[8], redE[8];

    uint4 wr[16];
#pragma unroll
    for (int kk = 0; kk < 16; ++kk)
        wr[kk] = *(const uint4*)(d_Ur16 + (k0 + kk) * H + j0);

    {
        const uint4* src = (const uint4*)d_Uh16;
        uint4* dst = (uint4*)Uh_s;
        for (int i = tid; i < H*H/8; i += 512) dst[i] = src[i];
    }
    if (tid < H) h2_s[tid] = __float2half2_rn(0.f);

    const int len = input_len[b];
    const float* __restrict__ xb = d_xrh + (size_t)b * T * (2*H);

    float ws2 = 0.f, we2 = 0.f, xr_c = 0.f, xh_c = 0.f, g_c = 0.f;
    float hj = 0.f, msb = 0.f, meb = 0.f;
    if (tid < H) {
        ws2  = Ws[H + tid];
        we2  = We[H + tid];
        xr_c = xb[tid];
        xh_c = xb[H + tid];
        g_c  = d_g[b*T];
    }
    if (tid == 0) { msb = d_ms[b] + bs[0]; meb = d_me[b] + be[0]; }
    __syncthreads();

    const __half* __restrict__ UhP = Uh_s + k0 * H + j0;
    const __half2 hz = __float2half2_rn(0.f);

    float xr_n = 0.f, xh_n = 0.f, g_n = 0.f;
    for (int t = 0; t < len; ++t) {
        {
            __half2 aE0 = hz, aE1 = hz, aE2 = hz, aE3 = hz;
            __half2 aO0 = hz, aO1 = hz, aO2 = hz, aO3 = hz;
#pragma unroll
            for (int kk = 0; kk < 16; ++kk) {
                const uint4 w = wr[kk];
                const __half2 hk = h2_s[k0 + kk];
                __half2 w0 = *(const __half2*)&w.x, w1 = *(const __half2*)&w.y;
                __half2 w2 = *(const __half2*)&w.z, w3 = *(const __half2*)&w.w;
                if (kk & 1) {
                    aO0 = __hfma2(w0, hk, aO0); aO1 = __hfma2(w1, hk, aO1);
                    aO2 = __hfma2(w2, hk, aO2); aO3 = __hfma2(w3, hk, aO3);
                } else {
                    aE0 = __hfma2(w0, hk, aE0); aE1 = __hfma2(w1, hk, aE1);
                    aE2 = __hfma2(w2, hk, aE2); aE3 = __hfma2(w3, hk, aE3);
                }
            }
            drain8(aE0, aE1, aE2, aE3, aO0, aO1, aO2, aO3, &red[kg][j0]);
        }
        __syncthreads();

        if (tid < H) {
            float s = xr_c;
#pragma unroll
            for (int g = 0; g < 16; ++g) s += red[g][tid];
            const float r = 1.0f / (1.0f + expf(-s));
            rh2_s[tid] = __float2half2_rn(r * hj);
            const int tn = (t + 1 < T) ? (t + 1) : (T - 1);
            xr_n = xb[tn*(2*H) + tid];
            xh_n = xb[tn*(2*H) + H + tid];
            g_n  = d_g[b*T + tn];
        }
        __syncthreads();

        {
            __half2 aE0 = hz, aE1 = hz, aE2 = hz, aE3 = hz;
            __half2 aO0 = hz, aO1 = hz, aO2 = hz, aO3 = hz;
#pragma unroll
            for (int kk = 0; kk < 16; ++kk) {
                const uint4 w = *(const uint4*)(UhP + kk * H);
                const __half2 hk = rh2_s[k0 + kk];
                __half2 w0 = *(const __half2*)&w.x, w1 = *(const __half2*)&w.y;
                __half2 w2 = *(const __half2*)&w.z, w3 = *(const __half2*)&w.w;
                if (kk & 1) {
                    aO0 = __hfma2(w0, hk, aO0); aO1 = __hfma2(w1, hk, aO1);
                    aO2 = __hfma2(w2, hk, aO2); aO3 = __hfma2(w3, hk, aO3);
                } else {
                    aE0 = __hfma2(w0, hk, aE0); aE1 = __hfma2(w1, hk, aE1);
                    aE2 = __hfma2(w2, hk, aE2); aE3 = __hfma2(w3, hk, aE3);
                }
            }
            drain8(aE0, aE1, aE2, aE3, aO0, aO1, aO2, aO3, &red[kg][j0]);
        }
        __syncthreads();

        if (tid < H) {
            float s = xh_c;
#pragma unroll
            for (int g = 0; g < 16; ++g) s += red[g][tid];
            const float hc = tanhf(s);
            const float hn = fmaf(g_c, hc - hj, hj);
            hj = hn;
            h2_s[tid] = __float2half2_rn(hn);
            float ps = hn * ws2, pe = hn * we2;
#pragma unroll
            for (int off = 16; off; off >>= 1) {
                ps += __shfl_xor_sync(0xffffffffu, ps, off);
                pe += __shfl_xor_sync(0xffffffffu, pe, off);
            }
            if (jl == 0) { redS[tid >> 5] = ps; redE[tid >> 5] = pe; }
            xr_c = xr_n; xh_c = xh_n; g_c = g_n;
        }
        __syncthreads();

        if (tid == 0) {
            float s = 0.f, se = 0.f;
#pragma unroll
            for (int w = 0; w < 8; ++w) { s += redS[w]; se += redE[w]; }
            out[b*T + t]       = tanhf(msb + s);
            out[B*T + b*T + t] = tanhf(meb + se);
        }
    }

    {
        const float cs = tanhf(d_ms[b] + bs[0]);
        const float ce = tanhf(d_me[b] + be[0]);
        for (int i = len + tid; i < T; i += 512) {
            out[b*T + i]       = cs;
            out[B*T + b*T + i] = ce;
        }
    }
}

// ---------------- entry point ----------------
extern "C" void kernel_launch(void* const* d_in, const int* in_sizes, int n_in,
                              void* d_out, int out_size)
{
    const float* qv   = (const float*)d_in[0];
    const float* fact = (const float*)d_in[1];
    const int*   ilen = (const int*)  d_in[2];
    const float* W1   = (const float*)d_in[3];
    const float* b1   = (const float*)d_in[4];
    const float* W2   = (const float*)d_in[5];
    const float* b2   = (const float*)d_in[6];
    const float* Wr   = (const float*)d_in[7];
    const float* Ur   = (const float*)d_in[8];
    const float* br   = (const float*)d_in[9];
    const float* Wh   = (const float*)d_in[10];
    const float* Uh   = (const float*)d_in[11];
    const float* bh   = (const float*)d_in[12];
    const float* Ws   = (const float*)d_in[13];
    const float* bs   = (const float*)d_in[14];
    const float* We   = (const float*)d_in[15];
    const float* be   = (const float*)d_in[16];
    float* out = (float*)d_out;

    const int uh_smem = H * H * (int)sizeof(__half);   // 128 KB dynamic
    static int attr_done = 0;
    if (!attr_done) {
        cudaFuncSetAttribute(recurrence_kernel,
                             cudaFuncAttributeMaxDynamicSharedMemorySize, uh_smem);
        attr_done = 1;
    }

    prep_w_kernel<<<256, 256>>>(W1);
    prep_u16_kernel<<<256, 256>>>(Ur, Uh, Wr, Wh);
    prep_batch_kernel<<<64, 256>>>(qv, W1, b1, Ws, We);
    gemm_xrh16_kernel<<<dim3(512, 8), 256>>>(fact, br, bh);
    gemm_att16_kernel<<<dim3(512, 4), 256>>>(fact, qv);
    att_dot_kernel<<<4096, 256>>>(W2, b2);
    softmax_kernel<<<64, 256>>>();
    recurrence_kernel<<<64, 512, uh_smem>>>(ilen, Ws, bs, We, be, out);
}

// round 15
// speedup vs baseline: 3.1327x; 1.3737x over previous
#include <cuda_runtime.h>
#include <cuda_fp16.h>
#include <math.h>
#include <stdint.h>

#define H 256
#define T 512
#define B 64
#define M_TOT (B*T)   // 32768

#define SWZ(o) ((o) ^ (((o) >> 3) & 0x70))   // SW128 swizzle on byte offsets

// ---------------- scratch (static device globals; no allocation) ----------------
__device__ float d_attpre[B*H];         // q@(W1[H:2H]+W1[2H:3H]) + b1
__device__ float d_ms[B];               // q . Ws[0:H]
__device__ float d_me[B];               // q . We[0:H]
__device__ float d_att[M_TOT];          // logits
__device__ float d_g[M_TOT];            // softmax gates
__device__ float d_xrh[(size_t)M_TOT*2*H]; // [m][0:256]=x@Wr+br, [256:512]=x@Wh+bh
__device__ __align__(16) __half d_Ur16[H*H];   // fp16 Ur  [k][j]
__device__ __align__(16) __half d_Uh16[H*H];   // fp16 Uh  [k][j]
__device__ __align__(16) __half d_Wr16[H*H];   // fp16 Wr
__device__ __align__(16) __half d_Wh16[H*H];   // fp16 Wh
__device__ __align__(16) __half d_W1f16[H*H];  // fp16 W1 rows [0,H)
__device__ __align__(16) __half d_Wfq16[H*H];  // fp16 (W1[3H:4H]+W1[4H:5H])
__device__ __align__(16) __half d_Wabs16[H*H]; // fp16 (W1[5H:6H]+W1[6H:7H])
__device__ __align__(16) __half d_V16[M_TOT*H]; // tanh(feats@W1+b1) in fp16

// ---------------- mma/ldmatrix helpers ----------------
static __device__ __forceinline__ void ldsm_x4(uint32_t addr, uint32_t* r) {
    asm volatile("ldmatrix.sync.aligned.m8n8.x4.shared.b16 {%0,%1,%2,%3}, [%4];"
                 : "=r"(r[0]), "=r"(r[1]), "=r"(r[2]), "=r"(r[3]) : "r"(addr));
}
static __device__ __forceinline__ void ldsm_x4_trans(uint32_t addr, uint32_t* r) {
    asm volatile("ldmatrix.sync.aligned.m8n8.x4.trans.shared.b16 {%0,%1,%2,%3}, [%4];"
                 : "=r"(r[0]), "=r"(r[1]), "=r"(r[2]), "=r"(r[3]) : "r"(addr));
}
static __device__ __forceinline__ void mma16816(
    float* d, const uint32_t* a, uint32_t b0, uint32_t b1) {
    asm volatile(
        "mma.sync.aligned.m16n8k16.row.col.f32.f16.f16.f32 "
        "{%0,%1,%2,%3}, {%4,%5,%6,%7}, {%8,%9}, {%0,%1,%2,%3};"
        : "+f"(d[0]), "+f"(d[1]), "+f"(d[2]), "+f"(d[3])
        : "r"(a[0]), "r"(a[1]), "r"(a[2]), "r"(a[3]), "r"(b0), "r"(b1));
}

// ---------------- K0: fp16 weight prep (W1 slices) ----------------
__global__ __launch_bounds__(256) void prep_w_kernel(const float* __restrict__ W1)
{
    int i = blockIdx.x * 256 + threadIdx.x;           // 65536 total
    d_W1f16[i]  = __float2half(W1[i]);                             // rows [0,H)
    d_Wfq16[i]  = __float2half(W1[196608 + i] + W1[262144 + i]);   // [3H,4H)+[4H,5H)
    d_Wabs16[i] = __float2half(W1[327680 + i] + W1[393216 + i]);   // [5H,6H)+[6H,7H)
}

// ---------------- K0b: fp16 conversion of Ur/Uh/Wr/Wh ----------------
__global__ __launch_bounds__(256) void prep_u16_kernel(
    const float* __restrict__ Ur, const float* __restrict__ Uh,
    const float* __restrict__ Wr, const float* __restrict__ Wh)
{
    int i = blockIdx.x * 256 + threadIdx.x;           // 65536 total
    d_Ur16[i] = __float2half(Ur[i]);
    d_Uh16[i] = __float2half(Uh[i]);
    d_Wr16[i] = __float2half(Wr[i]);
    d_Wh16[i] = __float2half(Wh[i]);
}

// ---------------- K1: per-batch precompute (fp32, exact) ----------------
__global__ __launch_bounds__(256) void prep_batch_kernel(
    const float* __restrict__ qv, const float* __restrict__ W1,
    const float* __restrict__ b1, const float* __restrict__ Ws,
    const float* __restrict__ We)
{
    const int b = blockIdx.x, j = threadIdx.x;
    __shared__ float qs[H];
    __shared__ float redS[8], redE[8];
    qs[j] = qv[b*H + j];
    __syncthreads();

    float acc = 0.f;
#pragma unroll 8
    for (int k = 0; k < H; ++k)
        acc += qs[k] * (W1[(H + k)*H + j] + W1[(2*H + k)*H + j]);
    d_attpre[b*H + j] = acc + b1[j];

    float ps = qs[j] * Ws[j];
    float pe = qs[j] * We[j];
#pragma unroll
    for (int off = 16; off; off >>= 1) {
        ps += __shfl_xor_sync(0xffffffffu, ps, off);
        pe += __shfl_xor_sync(0xffffffffu, pe, off);
    }
    if ((j & 31) == 0) { redS[j >> 5] = ps; redE[j >> 5] = pe; }
    __syncthreads();
    if (j == 0) {
        float s = 0.f, se = 0.f;
#pragma unroll
        for (int w = 0; w < 8; ++w) { s += redS[w]; se += redE[w]; }
        d_ms[b] = s;
        d_me[b] = se;
    }
}

// ---------------- K2a: attention GEMM via tensor cores ----------------
// C[m,n] = sum over 3 virtual K-slabs (f, f*q, |f-q|) of A @ W; then tanh(+attpre).
// Block 128m x 64n, 8 warps (4m x 2n), warp 32x32. SW128 smem, ldmatrix + HMMA.
__global__ __launch_bounds__(256) void gemm_att_mma(
    const float* __restrict__ fact, const float* __restrict__ qv)
{
    __shared__ __align__(16) __half As[128*64];   // 16 KB
    __shared__ __align__(16) __half Bs[64*64];    // 8 KB
    const int tid  = threadIdx.x;
    const int m0   = blockIdx.x * 128;            // 128 rows: same batch (512/128=4)
    const int n0   = blockIdx.y * 64;
    const int b    = m0 >> 9;
    const int w    = tid >> 5, lane = tid & 31;
    const int mw   = (w & 3) * 32, nw = (w >> 2) * 32;
    const int lrow = lane & 15, lhi = lane >> 4;

    const uint32_t asb = (uint32_t)__cvta_generic_to_shared(As);
    const uint32_t bsb = (uint32_t)__cvta_generic_to_shared(Bs);

    float acc[2][4][4];
#pragma unroll
    for (int mt = 0; mt < 2; ++mt)
#pragma unroll
        for (int nt = 0; nt < 4; ++nt)
#pragma unroll
            for (int i = 0; i < 4; ++i) acc[mt][nt][i] = 0.f;

    for (int sel = 0; sel < 3; ++sel) {
        const __half* __restrict__ W16 =
            (sel == 0) ? d_W1f16 : (sel == 1) ? d_Wfq16 : d_Wabs16;
        for (int kp0 = 0; kp0 < H; kp0 += 64) {
            // ---- fill As: 128 rows x 8 groups of 8 halves (transform fp32->fp16)
#pragma unroll
            for (int i = 0; i < 4; ++i) {
                int gi = tid + 256 * i;
                int r = gi >> 3, g = gi & 7;
                const float* fp = fact + (size_t)(m0 + r) * H + kp0 + g * 8;
                const float* qp = qv + b * H + kp0 + g * 8;
                float4 fa = *(const float4*)fp, fb = *(const float4*)(fp + 4);
                float4 qa = *(const float4*)qp, qb = *(const float4*)(qp + 4);
                float v[8];
                if (sel == 0) {
                    v[0]=fa.x; v[1]=fa.y; v[2]=fa.z; v[3]=fa.w;
                    v[4]=fb.x; v[5]=fb.y; v[6]=fb.z; v[7]=fb.w;
                } else if (sel == 1) {
                    v[0]=fa.x*qa.x; v[1]=fa.y*qa.y; v[2]=fa.z*qa.z; v[3]=fa.w*qa.w;
                    v[4]=fb.x*qb.x; v[5]=fb.y*qb.y; v[6]=fb.z*qb.z; v[7]=fb.w*qb.w;
                } else {
                    v[0]=fabsf(fa.x-qa.x); v[1]=fabsf(fa.y-qa.y);
                    v[2]=fabsf(fa.z-qa.z); v[3]=fabsf(fa.w-qa.w);
                    v[4]=fabsf(fb.x-qb.x); v[5]=fabsf(fb.y-qb.y);
                    v[6]=fabsf(fb.z-qb.z); v[7]=fabsf(fb.w-qb.w);
                }
                __half hv[8];
#pragma unroll
                for (int q = 0; q < 8; ++q) hv[q] = __float2half(v[q]);
                *(uint4*)((char*)As + SWZ(r * 128 + g * 16)) = *(uint4*)hv;
            }
            // ---- fill Bs: 64 rows(k) x 8 groups (already fp16)
#pragma unroll
            for (int i = 0; i < 2; ++i) {
                int gi = tid + 256 * i;
                int r = gi >> 3, g = gi & 7;
                uint4 vb = *(const uint4*)(W16 + (size_t)(kp0 + r) * H + n0 + g * 8);
                *(uint4*)((char*)Bs + SWZ(r * 128 + g * 16)) = vb;
            }
            __syncthreads();

#pragma unroll
            for (int kk = 0; kk < 64; kk += 16) {
                uint32_t afr[2][4], bfr[2][4];
#pragma unroll
                for (int mt = 0; mt < 2; ++mt) {
                    int row = mw + mt * 16 + lrow;
                    ldsm_x4(asb + SWZ(row * 128 + kk * 2 + lhi * 16), afr[mt]);
                }
#pragma unroll
                for (int nt = 0; nt < 2; ++nt) {
                    int row = kk + lrow;
                    int nc  = nw + nt * 16 + lhi * 8;
                    ldsm_x4_trans(bsb + SWZ(row * 128 + nc * 2), bfr[nt]);
                }
#pragma unroll
                for (int mt = 0; mt < 2; ++mt)
#pragma unroll
                    for (int nt = 0; nt < 2; ++nt) {
                        mma16816(acc[mt][nt*2+0], afr[mt], bfr[nt][0], bfr[nt][1]);
                        mma16816(acc[mt][nt*2+1], afr[mt], bfr[nt][2], bfr[nt][3]);
                    }
            }
            __syncthreads();
        }
    }

    // ---- epilogue: tanh(acc + attpre), store half2
    const int r0 = lane >> 2;
    const int c0 = (lane & 3) * 2;
#pragma unroll
    for (int mt = 0; mt < 2; ++mt)
#pragma unroll
        for (int nt8 = 0; nt8 < 4; ++nt8) {
            int m = m0 + mw + mt * 16 + r0;
            int n = n0 + nw + nt8 * 8 + c0;
            float p0 = d_attpre[b*H + n], p1 = d_attpre[b*H + n + 1];
            float* a4 = acc[mt][nt8];
            __half2 h01 = __floats2half2_rn(tanhf(a4[0] + p0), tanhf(a4[1] + p1));
            __half2 h23 = __floats2half2_rn(tanhf(a4[2] + p0), tanhf(a4[3] + p1));
            *(__half2*)(d_V16 + (size_t)m * H + n)       = h01;
            *(__half2*)(d_V16 + (size_t)(m + 8) * H + n) = h23;
        }
}

// ---------------- K3: XRH GEMM via tensor cores (N=512 = [Wr|Wh]) ----------------
__global__ __launch_bounds__(256) void gemm_xrh_mma(
    const float* __restrict__ fact,
    const float* __restrict__ br, const float* __restrict__ bh)
{
    __shared__ __align__(16) __half As[128*64];
    __shared__ __align__(16) __half Bs[64*64];
    const int tid  = threadIdx.x;
    const int m0   = blockIdx.x * 128;
    const int n0   = blockIdx.y * 64;            // [0,512)
    const int w    = tid >> 5, lane = tid & 31;
    const int mw   = (w & 3) * 32, nw = (w >> 2) * 32;
    const int lrow = lane & 15, lhi = lane >> 4;

    const bool isR = (n0 < H);
    const __half* __restrict__ W16  = isR ? d_Wr16 : d_Wh16;
    const float*  __restrict__ bias = isR ? br : bh;
    const int nb = isR ? n0 : n0 - H;

    const uint32_t asb = (uint32_t)__cvta_generic_to_shared(As);
    const uint32_t bsb = (uint32_t)__cvta_generic_to_shared(Bs);

    float acc[2][4][4];
#pragma unroll
    for (int mt = 0; mt < 2; ++mt)
#pragma unroll
        for (int nt = 0; nt < 4; ++nt)
#pragma unroll
            for (int i = 0; i < 4; ++i) acc[mt][nt][i] = 0.f;

    for (int kp0 = 0; kp0 < H; kp0 += 64) {
#pragma unroll
        for (int i = 0; i < 4; ++i) {
            int gi = tid + 256 * i;
            int r = gi >> 3, g = gi & 7;
            const float* fp = fact + (size_t)(m0 + r) * H + kp0 + g * 8;
            float4 fa = *(const float4*)fp, fb = *(const float4*)(fp + 4);
            __half hv[8];
            hv[0]=__float2half(fa.x); hv[1]=__float2half(fa.y);
            hv[2]=__float2half(fa.z); hv[3]=__float2half(fa.w);
            hv[4]=__float2half(fb.x); hv[5]=__float2half(fb.y);
            hv[6]=__float2half(fb.z); hv[7]=__float2half(fb.w);
            *(uint4*)((char*)As + SWZ(r * 128 + g * 16)) = *(uint4*)hv;
        }
#pragma unroll
        for (int i = 0; i < 2; ++i) {
            int gi = tid + 256 * i;
            int r = gi >> 3, g = gi & 7;
            uint4 vb = *(const uint4*)(W16 + (size_t)(kp0 + r) * H + nb + g * 8);
            *(uint4*)((char*)Bs + SWZ(r * 128 + g * 16)) = vb;
        }
        __syncthreads();

#pragma unroll
        for (int kk = 0; kk < 64; kk += 16) {
            uint32_t afr[2][4], bfr[2][4];
#pragma unroll
            for (int mt = 0; mt < 2; ++mt) {
                int row = mw + mt * 16 + lrow;
                ldsm_x4(asb + SWZ(row * 128 + kk * 2 + lhi * 16), afr[mt]);
            }
#pragma unroll
            for (int nt = 0; nt < 2; ++nt) {
                int row = kk + lrow;
                int nc  = nw + nt * 16 + lhi * 8;
                ldsm_x4_trans(bsb + SWZ(row * 128 + nc * 2), bfr[nt]);
            }
#pragma unroll
            for (int mt = 0; mt < 2; ++mt)
#pragma unroll
                for (int nt = 0; nt < 2; ++nt) {
                    mma16816(acc[mt][nt*2+0], afr[mt], bfr[nt][0], bfr[nt][1]);
                    mma16816(acc[mt][nt*2+1], afr[mt], bfr[nt][2], bfr[nt][3]);
                }
        }
        __syncthreads();
    }

    // ---- epilogue: +bias, store float2 into d_xrh (column n in [0,512))
    const int r0 = lane >> 2;
    const int c0 = (lane & 3) * 2;
#pragma unroll
    for (int mt = 0; mt < 2; ++mt)
#pragma unroll
        for (int nt8 = 0; nt8 < 4; ++nt8) {
            int m = m0 + mw + mt * 16 + r0;
            int nl = nw + nt8 * 8 + c0;          // local col in [0,64)
            int n  = n0 + nl;                    // global col in [0,512)
            float b0v = bias[nb + nl], b1v = bias[nb + nl + 1];
            float* a4 = acc[mt][nt8];
            *(float2*)(d_xrh + (size_t)m * (2*H) + n) =
                make_float2(a4[0] + b0v, a4[1] + b1v);
            *(float2*)(d_xrh + (size_t)(m + 8) * (2*H) + n) =
                make_float2(a4[2] + b0v, a4[3] + b1v);
        }
}

// ---------------- K2b: att[m] = V16[m] . W2 + b2 ----------------
__global__ __launch_bounds__(256) void att_dot_kernel(
    const float* __restrict__ W2, const float* __restrict__ b2)
{
    const int row  = blockIdx.x * 8 + (threadIdx.x >> 5);
    const int lane = threadIdx.x & 31;
    uint4 v = *(const uint4*)(d_V16 + (size_t)row*H + lane*8);
    const __half2* vh = (const __half2*)&v;
    float s = 0.f;
#pragma unroll
    for (int i = 0; i < 4; ++i) {
        float2 f = __half22float2(vh[i]);
        s += f.x * W2[lane*8 + 2*i] + f.y * W2[lane*8 + 2*i + 1];
    }
#pragma unroll
    for (int off = 16; off; off >>= 1) s += __shfl_xor_sync(0xffffffffu, s, off);
    if (lane == 0) d_att[row] = s + b2[0];
}

// ---------------- K4: softmax over T per batch ----------------
__global__ __launch_bounds__(256) void softmax_kernel()
{
    const int b = blockIdx.x, tid = threadIdx.x;
    __shared__ float sd[256];
    float x0 = d_att[b*T + tid];
    float x1 = d_att[b*T + 256 + tid];
    sd[tid] = fmaxf(x0, x1);
    __syncthreads();
    for (int s = 128; s; s >>= 1) {
        if (tid < s) sd[tid] = fmaxf(sd[tid], sd[tid + s]);
        __syncthreads();
    }
    const float M = sd[0];
    __syncthreads();
    float e0 = expf(x0 - M), e1 = expf(x1 - M);
    sd[tid] = e0 + e1;
    __syncthreads();
    for (int s = 128; s; s >>= 1) {
        if (tid < s) sd[tid] += sd[tid + s];
        __syncthreads();
    }
    const float inv = 1.0f / sd[0];
    d_g[b*T + tid]       = e0 * inv;
    d_g[b*T + 256 + tid] = e1 * inv;
}

// ---------------- K5: GRU recurrence — Ur in REGISTERS, Uh in SMEM (unchanged) ----------------
__device__ __forceinline__ void drain8(
    __half2 aE0, __half2 aE1, __half2 aE2, __half2 aE3,
    __half2 aO0, __half2 aO1, __half2 aO2, __half2 aO3,
    float* __restrict__ redrow)
{
    float2 e0 = __half22float2(aE0), o0 = __half22float2(aO0);
    float2 e1 = __half22float2(aE1), o1 = __half22float2(aO1);
    float2 e2 = __half22float2(aE2), o2 = __half22float2(aO2);
    float2 e3 = __half22float2(aE3), o3 = __half22float2(aO3);
    *(float4*)redrow       = make_float4(e0.x+o0.x, e0.y+o0.y, e1.x+o1.x, e1.y+o1.y);
    *(float4*)(redrow + 4) = make_float4(e2.x+o2.x, e2.y+o2.y, e3.x+o3.x, e3.y+o3.y);
}

__global__ __launch_bounds__(512) void recurrence_kernel(
    const int* __restrict__ input_len,
    const float* __restrict__ Ws, const float* __restrict__ bs,
    const float* __restrict__ We, const float* __restrict__ be,
    float* __restrict__ out)
{
    extern __shared__ __half Uh_s[];     // [H*H] fp16, 128 KB
    const int b   = blockIdx.x;
    const int tid = threadIdx.x;
    const int kg  = tid >> 5;            // warp = k-group
    const int jl  = tid & 31;
    const int j0  = jl * 8;
    const int k0  = kg * 16;

    __shared__ __half2 h2_s[H];          // duplicated-pair h
    __shared__ __half2 rh2_s[H];         // duplicated-pair r*h
    __shared__ float   red[16][H];       // 16 KB partials
    __shared__ float   redS[8], redE[8];

    uint4 wr[16];
#pragma unroll
    for (int kk = 0; kk < 16; ++kk)
        wr[kk] = *(const uint4*)(d_Ur16 + (k0 + kk) * H + j0);

    {
        const uint4* src = (const uint4*)d_Uh16;
        uint4* dst = (uint4*)Uh_s;
        for (int i = tid; i < H*H/8; i += 512) dst[i] = src[i];
    }
    if (tid < H) h2_s[tid] = __float2half2_rn(0.f);

    const int len = input_len[b];
    const float* __restrict__ xb = d_xrh + (size_t)b * T * (2*H);

    float ws2 = 0.f, we2 = 0.f, xr_c = 0.f, xh_c = 0.f, g_c = 0.f;
    float hj = 0.f, msb = 0.f, meb = 0.f;
    if (tid < H) {
        ws2  = Ws[H + tid];
        we2  = We[H + tid];
        xr_c = xb[tid];
        xh_c = xb[H + tid];
        g_c  = d_g[b*T];
    }
    if (tid == 0) { msb = d_ms[b] + bs[0]; meb = d_me[b] + be[0]; }
    __syncthreads();

    const __half* __restrict__ UhP = Uh_s + k0 * H + j0;
    const __half2 hz = __float2half2_rn(0.f);

    float xr_n = 0.f, xh_n = 0.f, g_n = 0.f;
    for (int t = 0; t < len; ++t) {
        {
            __half2 aE0 = hz, aE1 = hz, aE2 = hz, aE3 = hz;
            __half2 aO0 = hz, aO1 = hz, aO2 = hz, aO3 = hz;
#pragma unroll
            for (int kk = 0; kk < 16; ++kk) {
                const uint4 w2v = wr[kk];
                const __half2 hk = h2_s[k0 + kk];
                __half2 w0 = *(const __half2*)&w2v.x, w1 = *(const __half2*)&w2v.y;
                __half2 w2 = *(const __half2*)&w2v.z, w3 = *(const __half2*)&w2v.w;
                if (kk & 1) {
                    aO0 = __hfma2(w0, hk, aO0); aO1 = __hfma2(w1, hk, aO1);
                    aO2 = __hfma2(w2, hk, aO2); aO3 = __hfma2(w3, hk, aO3);
                } else {
                    aE0 = __hfma2(w0, hk, aE0); aE1 = __hfma2(w1, hk, aE1);
                    aE2 = __hfma2(w2, hk, aE2); aE3 = __hfma2(w3, hk, aE3);
                }
            }
            drain8(aE0, aE1, aE2, aE3, aO0, aO1, aO2, aO3, &red[kg][j0]);
        }
        __syncthreads();

        if (tid < H) {
            float s = xr_c;
#pragma unroll
            for (int g = 0; g < 16; ++g) s += red[g][tid];
            const float r = 1.0f / (1.0f + expf(-s));
            rh2_s[tid] = __float2half2_rn(r * hj);
            const int tn = (t + 1 < T) ? (t + 1) : (T - 1);
            xr_n = xb[tn*(2*H) + tid];
            xh_n = xb[tn*(2*H) + H + tid];
            g_n  = d_g[b*T + tn];
        }
        __syncthreads();

        {
            __half2 aE0 = hz, aE1 = hz, aE2 = hz, aE3 = hz;
            __half2 aO0 = hz, aO1 = hz, aO2 = hz, aO3 = hz;
#pragma unroll
            for (int kk = 0; kk < 16; ++kk) {
                const uint4 w2v = *(const uint4*)(UhP + kk * H);
                const __half2 hk = rh2_s[k0 + kk];
                __half2 w0 = *(const __half2*)&w2v.x, w1 = *(const __half2*)&w2v.y;
                __half2 w2 = *(const __half2*)&w2v.z, w3 = *(const __half2*)&w2v.w;
                if (kk & 1) {
                    aO0 = __hfma2(w0, hk, aO0); aO1 = __hfma2(w1, hk, aO1);
                    aO2 = __hfma2(w2, hk, aO2); aO3 = __hfma2(w3, hk, aO3);
                } else {
                    aE0 = __hfma2(w0, hk, aE0); aE1 = __hfma2(w1, hk, aE1);
                    aE2 = __hfma2(w2, hk, aE2); aE3 = __hfma2(w3, hk, aE3);
                }
            }
            drain8(aE0, aE1, aE2, aE3, aO0, aO1, aO2, aO3, &red[kg][j0]);
        }
        __syncthreads();

        if (tid < H) {
            float s = xh_c;
#pragma unroll
            for (int g = 0; g < 16; ++g) s += red[g][tid];
            const float hc = tanhf(s);
            const float hn = fmaf(g_c, hc - hj, hj);
            hj = hn;
            h2_s[tid] = __float2half2_rn(hn);
            float ps = hn * ws2, pe = hn * we2;
#pragma unroll
            for (int off = 16; off; off >>= 1) {
                ps += __shfl_xor_sync(0xffffffffu, ps, off);
                pe += __shfl_xor_sync(0xffffffffu, pe, off);
            }
            if (jl == 0) { redS[tid >> 5] = ps; redE[tid >> 5] = pe; }
            xr_c = xr_n; xh_c = xh_n; g_c = g_n;
        }
        __syncthreads();

        if (tid == 0) {
            float s = 0.f, se = 0.f;
#pragma unroll
            for (int w = 0; w < 8; ++w) { s += redS[w]; se += redE[w]; }
            out[b*T + t]       = tanhf(msb + s);
            out[B*T + b*T + t] = tanhf(meb + se);
        }
    }

    {
        const float cs = tanhf(d_ms[b] + bs[0]);
        const float ce = tanhf(d_me[b] + be[0]);
        for (int i = len + tid; i < T; i += 512) {
            out[b*T + i]       = cs;
            out[B*T + b*T + i] = ce;
        }
    }
}

// ---------------- entry point ----------------
extern "C" void kernel_launch(void* const* d_in, const int* in_sizes, int n_in,
                              void* d_out, int out_size)
{
    const float* qv   = (const float*)d_in[0];
    const float* fact = (const float*)d_in[1];
    const int*   ilen = (const int*)  d_in[2];
    const float* W1   = (const float*)d_in[3];
    const float* b1   = (const float*)d_in[4];
    const float* W2   = (const float*)d_in[5];
    const float* b2   = (const float*)d_in[6];
    const float* Wr   = (const float*)d_in[7];
    const float* Ur   = (const float*)d_in[8];
    const float* br   = (const float*)d_in[9];
    const float* Wh   = (const float*)d_in[10];
    const float* Uh   = (const float*)d_in[11];
    const float* bh   = (const float*)d_in[12];
    const float* Ws   = (const float*)d_in[13];
    const float* bs   = (const float*)d_in[14];
    const float* We   = (const float*)d_in[15];
    const float* be   = (const float*)d_in[16];
    float* out = (float*)d_out;

    const int uh_smem = H * H * (int)sizeof(__half);   // 128 KB dynamic
    static int attr_done = 0;
    if (!attr_done) {
        cudaFuncSetAttribute(recurrence_kernel,
                             cudaFuncAttributeMaxDynamicSharedMemorySize, uh_smem);
        attr_done = 1;
    }

    prep_w_kernel<<<256, 256>>>(W1);
    prep_u16_kernel<<<256, 256>>>(Ur, Uh, Wr, Wh);
    prep_batch_kernel<<<64, 256>>>(qv, W1, b1, Ws, We);
    gemm_xrh_mma<<<dim3(256, 8), 256>>>(fact, br, bh);
    gemm_att_mma<<<dim3(256, 4), 256>>>(fact, qv);
    att_dot_kernel<<<4096, 256>>>(W2, b2);
    softmax_kernel<<<64, 256>>>();
    recurrence_kernel<<<64, 512, uh_smem>>>(ilen, Ws, bs, We, be, out);
}

// round 17
// speedup vs baseline: 3.3148x; 1.0581x over previous
#include <cuda_runtime.h>
#include <cuda_fp16.h>
#include <math.h>
#include <stdint.h>

#define H 256
#define T 512
#define B 64
#define M_TOT (B*T)   // 32768

#define SWZ(o) ((o) ^ (((o) >> 3) & 0x70))   // SW128 swizzle on byte offsets

// ---------------- scratch (static device globals; no allocation) ----------------
__device__ float d_attpre[B*H];         // q@(W1[H:2H]+W1[2H:3H]) + b1
__device__ float d_ms[B];               // q . Ws[0:H]
__device__ float d_me[B];               // q . We[0:H]
__device__ float d_att[M_TOT];          // logits (atomic-accumulated; b2 omitted — softmax shift-invariant)
__device__ float d_g[M_TOT];            // softmax gates
__device__ float d_xrh[(size_t)M_TOT*2*H]; // [m][0:256]=x@Wr+br, [256:512]=x@Wh+bh
__device__ __align__(16) __half d_Ur16[H*H];   // fp16 Ur  [k][j]
__device__ __align__(16) __half d_Uh16[H*H];   // fp16 Uh  [k][j]
__device__ __align__(16) __half d_Wr16[H*H];   // fp16 Wr
__device__ __align__(16) __half d_Wh16[H*H];   // fp16 Wh
__device__ __align__(16) __half d_W1f16[H*H];  // fp16 W1 rows [0,H)
__device__ __align__(16) __half d_Wfq16[H*H];  // fp16 (W1[3H:4H]+W1[4H:5H])
__device__ __align__(16) __half d_Wabs16[H*H]; // fp16 (W1[5H:6H]+W1[6H:7H])

// ---------------- mma/ldmatrix helpers ----------------
static __device__ __forceinline__ void ldsm_x4(uint32_t addr, uint32_t* r) {
    asm volatile("ldmatrix.sync.aligned.m8n8.x4.shared.b16 {%0,%1,%2,%3}, [%4];"
                 : "=r"(r[0]), "=r"(r[1]), "=r"(r[2]), "=r"(r[3]) : "r"(addr));
}
static __device__ __forceinline__ void ldsm_x4_trans(uint32_t addr, uint32_t* r) {
    asm volatile("ldmatrix.sync.aligned.m8n8.x4.trans.shared.b16 {%0,%1,%2,%3}, [%4];"
                 : "=r"(r[0]), "=r"(r[1]), "=r"(r[2]), "=r"(r[3]) : "r"(addr));
}
static __device__ __forceinline__ void mma16816(
    float* d, const uint32_t* a, uint32_t b0, uint32_t b1) {
    asm volatile(
        "mma.sync.aligned.m16n8k16.row.col.f32.f16.f16.f32 "
        "{%0,%1,%2,%3}, {%4,%5,%6,%7}, {%8,%9}, {%0,%1,%2,%3};"
        : "+f"(d[0]), "+f"(d[1]), "+f"(d[2]), "+f"(d[3])
        : "r"(a[0]), "r"(a[1]), "r"(a[2]), "r"(a[3]), "r"(b0), "r"(b1));
}

// ---------------- K0: fp16 weight prep (W1 slices) ----------------
__global__ __launch_bounds__(256) void prep_w_kernel(const float* __restrict__ W1)
{
    int i = blockIdx.x * 256 + threadIdx.x;           // 65536 total
    d_W1f16[i]  = __float2half(W1[i]);                             // rows [0,H)
    d_Wfq16[i]  = __float2half(W1[196608 + i] + W1[262144 + i]);   // [3H,4H)+[4H,5H)
    d_Wabs16[i] = __float2half(W1[327680 + i] + W1[393216 + i]);   // [5H,6H)+[6H,7H)
}

// ---------------- K0b: fp16 conversion of Ur/Uh/Wr/Wh ----------------
__global__ __launch_bounds__(256) void prep_u16_kernel(
    const float* __restrict__ Ur, const float* __restrict__ Uh,
    const float* __restrict__ Wr, const float* __restrict__ Wh)
{
    int i = blockIdx.x * 256 + threadIdx.x;           // 65536 total
    d_Ur16[i] = __float2half(Ur[i]);
    d_Uh16[i] = __float2half(Uh[i]);
    d_Wr16[i] = __float2half(Wr[i]);
    d_Wh16[i] = __float2half(Wh[i]);
}

// ---------------- K1: per-batch precompute (fp32, exact) + d_att zeroing ----------------
__global__ __launch_bounds__(256) void prep_batch_kernel(
    const float* __restrict__ qv, const float* __restrict__ W1,
    const float* __restrict__ b1, const float* __restrict__ Ws,
    const float* __restrict__ We)
{
    const int b = blockIdx.x, j = threadIdx.x;
    __shared__ float qs[H];
    __shared__ float redS[8], redE[8];
    qs[j] = qv[b*H + j];
    d_att[b*T + j]       = 0.f;          // zero logits for atomic accumulation
    d_att[b*T + 256 + j] = 0.f;
    __syncthreads();

    float acc = 0.f;
#pragma unroll 8
    for (int k = 0; k < H; ++k)
        acc += qs[k] * (W1[(H + k)*H + j] + W1[(2*H + k)*H + j]);
    d_attpre[b*H + j] = acc + b1[j];

    float ps = qs[j] * Ws[j];
    float pe = qs[j] * We[j];
#pragma unroll
    for (int off = 16; off; off >>= 1) {
        ps += __shfl_xor_sync(0xffffffffu, ps, off);
        pe += __shfl_xor_sync(0xffffffffu, pe, off);
    }
    if ((j & 31) == 0) { redS[j >> 5] = ps; redE[j >> 5] = pe; }
    __syncthreads();
    if (j == 0) {
        float s = 0.f, se = 0.f;
#pragma unroll
        for (int w = 0; w < 8; ++w) { s += redS[w]; se += redE[w]; }
        d_ms[b] = s;
        d_me[b] = se;
    }
}

// ---------------- K2: attention GEMM (tensor cores) + FUSED W2 dot ----------------
// acc = feats @ W1 over 3 virtual K-slabs; att[m] += sum_n tanh(acc+attpre)*W2[n]
__global__ __launch_bounds__(256) void gemm_att_mma(
    const float* __restrict__ fact, const float* __restrict__ qv,
    const float* __restrict__ W2)
{
    __shared__ __align__(16) __half As[128*64];   // 16 KB
    __shared__ __align__(16) __half Bs[64*64];    // 8 KB
    const int tid  = threadIdx.x;
    const int m0   = blockIdx.x * 128;            // 128 rows: same batch (512/128=4)
    const int n0   = blockIdx.y * 64;
    const int b    = m0 >> 9;
    const int w    = tid >> 5, lane = tid & 31;
    const int mw   = (w & 3) * 32, nw = (w >> 2) * 32;
    const int lrow = lane & 15, lhi = lane >> 4;

    const uint32_t asb = (uint32_t)__cvta_generic_to_shared(As);
    const uint32_t bsb = (uint32_t)__cvta_generic_to_shared(Bs);

    float acc[2][4][4];
#pragma unroll
    for (int mt = 0; mt < 2; ++mt)
#pragma unroll
        for (int nt = 0; nt < 4; ++nt)
#pragma unroll
            for (int i = 0; i < 4; ++i) acc[mt][nt][i] = 0.f;

    for (int sel = 0; sel < 3; ++sel) {
        const __half* __restrict__ W16 =
            (sel == 0) ? d_W1f16 : (sel == 1) ? d_Wfq16 : d_Wabs16;
        for (int kp0 = 0; kp0 < H; kp0 += 64) {
#pragma unroll
            for (int i = 0; i < 4; ++i) {
                int gi = tid + 256 * i;
                int r = gi >> 3, g = gi & 7;
                const float* fp = fact + (size_t)(m0 + r) * H + kp0 + g * 8;
                const float* qp = qv + b * H + kp0 + g * 8;
                float4 fa = *(const float4*)fp, fb = *(const float4*)(fp + 4);
                float4 qa = *(const float4*)qp, qb = *(const float4*)(qp + 4);
                float v[8];
                if (sel == 0) {
                    v[0]=fa.x; v[1]=fa.y; v[2]=fa.z; v[3]=fa.w;
                    v[4]=fb.x; v[5]=fb.y; v[6]=fb.z; v[7]=fb.w;
                } else if (sel == 1) {
                    v[0]=fa.x*qa.x; v[1]=fa.y*qa.y; v[2]=fa.z*qa.z; v[3]=fa.w*qa.w;
                    v[4]=fb.x*qb.x; v[5]=fb.y*qb.y; v[6]=fb.z*qb.z; v[7]=fb.w*qb.w;
                } else {
                    v[0]=fabsf(fa.x-qa.x); v[1]=fabsf(fa.y-qa.y);
                    v[2]=fabsf(fa.z-qa.z); v[3]=fabsf(fa.w-qa.w);
                    v[4]=fabsf(fb.x-qb.x); v[5]=fabsf(fb.y-qb.y);
                    v[6]=fabsf(fb.z-qb.z); v[7]=fabsf(fb.w-qb.w);
                }
                __half hv[8];
#pragma unroll
                for (int q = 0; q < 8; ++q) hv[q] = __float2half(v[q]);
                *(uint4*)((char*)As + SWZ(r * 128 + g * 16)) = *(uint4*)hv;
            }
#pragma unroll
            for (int i = 0; i < 2; ++i) {
                int gi = tid + 256 * i;
                int r = gi >> 3, g = gi & 7;
                uint4 vb = *(const uint4*)(W16 + (size_t)(kp0 + r) * H + n0 + g * 8);
                *(uint4*)((char*)Bs + SWZ(r * 128 + g * 16)) = vb;
            }
            __syncthreads();

#pragma unroll
            for (int kk = 0; kk < 64; kk += 16) {
                uint32_t afr[2][4], bfr[2][4];
#pragma unroll
                for (int mt = 0; mt < 2; ++mt) {
                    int row = mw + mt * 16 + lrow;
                    ldsm_x4(asb + SWZ(row * 128 + kk * 2 + lhi * 16), afr[mt]);
                }
#pragma unroll
                for (int nt = 0; nt < 2; ++nt) {
                    int row = kk + lrow;
                    int nc  = nw + nt * 16 + lhi * 8;
                    ldsm_x4_trans(bsb + SWZ(row * 128 + nc * 2), bfr[nt]);
                }
#pragma unroll
                for (int mt = 0; mt < 2; ++mt)
#pragma unroll
                    for (int nt = 0; nt < 2; ++nt) {
                        mma16816(acc[mt][nt*2+0], afr[mt], bfr[nt][0], bfr[nt][1]);
                        mma16816(acc[mt][nt*2+1], afr[mt], bfr[nt][2], bfr[nt][3]);
                    }
            }
            __syncthreads();
        }
    }

    // ---- fused epilogue: tanh + W2 dot partial + atomicAdd to d_att
    const int r0 = lane >> 2;
    const int c0 = (lane & 3) * 2;
#pragma unroll
    for (int mt = 0; mt < 2; ++mt) {
        float ps0 = 0.f, ps1 = 0.f;
#pragma unroll
        for (int nt8 = 0; nt8 < 4; ++nt8) {
            int n = n0 + nw + nt8 * 8 + c0;
            float p0 = d_attpre[b*H + n], p1 = d_attpre[b*H + n + 1];
            float w20 = W2[n], w21 = W2[n + 1];
            float* a4 = acc[mt][nt8];
            ps0 += tanhf(a4[0] + p0) * w20 + tanhf(a4[1] + p1) * w21;
            ps1 += tanhf(a4[2] + p0) * w20 + tanhf(a4[3] + p1) * w21;
        }
        ps0 += __shfl_xor_sync(0xffffffffu, ps0, 1);
        ps0 += __shfl_xor_sync(0xffffffffu, ps0, 2);
        ps1 += __shfl_xor_sync(0xffffffffu, ps1, 1);
        ps1 += __shfl_xor_sync(0xffffffffu, ps1, 2);
        if ((lane & 3) == 0) {
            int m = m0 + mw + mt * 16 + r0;
            atomicAdd(&d_att[m], ps0);
            atomicAdd(&d_att[m + 8], ps1);
        }
    }
}

// ---------------- K3: XRH GEMM via tensor cores (N=512 = [Wr|Wh]) ----------------
__global__ __launch_bounds__(256) void gemm_xrh_mma(
    const float* __restrict__ fact,
    const float* __restrict__ br, const float* __restrict__ bh)
{
    __shared__ __align__(16) __half As[128*64];
    __shared__ __align__(16) __half Bs[64*64];
    const int tid  = threadIdx.x;
    const int m0   = blockIdx.x * 128;
    const int n0   = blockIdx.y * 64;            // [0,512)
    const int w    = tid >> 5, lane = tid & 31;
    const int mw   = (w & 3) * 32, nw = (w >> 2) * 32;
    const int lrow = lane & 15, lhi = lane >> 4;

    const bool isR = (n0 < H);
    const __half* __restrict__ W16  = isR ? d_Wr16 : d_Wh16;
    const float*  __restrict__ bias = isR ? br : bh;
    const int nb = isR ? n0 : n0 - H;

    const uint32_t asb = (uint32_t)__cvta_generic_to_shared(As);
    const uint32_t bsb = (uint32_t)__cvta_generic_to_shared(Bs);

    float acc[2][4][4];
#pragma unroll
    for (int mt = 0; mt < 2; ++mt)
#pragma unroll
        for (int nt = 0; nt < 4; ++nt)
#pragma unroll
            for (int i = 0; i < 4; ++i) acc[mt][nt][i] = 0.f;

    for (int kp0 = 0; kp0 < H; kp0 += 64) {
#pragma unroll
        for (int i = 0; i < 4; ++i) {
            int gi = tid + 256 * i;
            int r = gi >> 3, g = gi & 7;
            const float* fp = fact + (size_t)(m0 + r) * H + kp0 + g * 8;
            float4 fa = *(const float4*)fp, fb = *(const float4*)(fp + 4);
            __half hv[8];
            hv[0]=__float2half(fa.x); hv[1]=__float2half(fa.y);
            hv[2]=__float2half(fa.z); hv[3]=__float2half(fa.w);
            hv[4]=__float2half(fb.x); hv[5]=__float2half(fb.y);
            hv[6]=__float2half(fb.z); hv[7]=__float2half(fb.w);
            *(uint4*)((char*)As + SWZ(r * 128 + g * 16)) = *(uint4*)hv;
        }
#pragma unroll
        for (int i = 0; i < 2; ++i) {
            int gi = tid + 256 * i;
            int r = gi >> 3, g = gi & 7;
            uint4 vb = *(const uint4*)(W16 + (size_t)(kp0 + r) * H + nb + g * 8);
            *(uint4*)((char*)Bs + SWZ(r * 128 + g * 16)) = vb;
        }
        __syncthreads();

#pragma unroll
        for (int kk = 0; kk < 64; kk += 16) {
            uint32_t afr[2][4], bfr[2][4];
#pragma unroll
            for (int mt = 0; mt < 2; ++mt) {
                int row = mw + mt * 16 + lrow;
                ldsm_x4(asb + SWZ(row * 128 + kk * 2 + lhi * 16), afr[mt]);
            }
#pragma unroll
            for (int nt = 0; nt < 2; ++nt) {
                int row = kk + lrow;
                int nc  = nw + nt * 16 + lhi * 8;
                ldsm_x4_trans(bsb + SWZ(row * 128 + nc * 2), bfr[nt]);
            }
#pragma unroll
            for (int mt = 0; mt < 2; ++mt)
#pragma unroll
                for (int nt = 0; nt < 2; ++nt) {
                    mma16816(acc[mt][nt*2+0], afr[mt], bfr[nt][0], bfr[nt][1]);
                    mma16816(acc[mt][nt*2+1], afr[mt], bfr[nt][2], bfr[nt][3]);
                }
        }
        __syncthreads();
    }

    const int r0 = lane >> 2;
    const int c0 = (lane & 3) * 2;
#pragma unroll
    for (int mt = 0; mt < 2; ++mt)
#pragma unroll
        for (int nt8 = 0; nt8 < 4; ++nt8) {
            int m = m0 + mw + mt * 16 + r0;
            int nl = nw + nt8 * 8 + c0;          // local col in [0,64)
            int n  = n0 + nl;                    // global col in [0,512)
            float b0v = bias[nb + nl], b1v = bias[nb + nl + 1];
            float* a4 = acc[mt][nt8];
            *(float2*)(d_xrh + (size_t)m * (2*H) + n) =
                make_float2(a4[0] + b0v, a4[1] + b1v);
            *(float2*)(d_xrh + (size_t)(m + 8) * (2*H) + n) =
                make_float2(a4[2] + b0v, a4[3] + b1v);
        }
}

// ---------------- K4: softmax over T per batch ----------------
__global__ __launch_bounds__(256) void softmax_kernel()
{
    const int b = blockIdx.x, tid = threadIdx.x;
    __shared__ float sd[256];
    float x0 = d_att[b*T + tid];
    float x1 = d_att[b*T + 256 + tid];
    sd[tid] = fmaxf(x0, x1);
    __syncthreads();
    for (int s = 128; s; s >>= 1) {
        if (tid < s) sd[tid] = fmaxf(sd[tid], sd[tid + s]);
        __syncthreads();
    }
    const float M = sd[0];
    __syncthreads();
    float e0 = expf(x0 - M), e1 = expf(x1 - M);
    sd[tid] = e0 + e1;
    __syncthreads();
    for (int s = 128; s; s >>= 1) {
        if (tid < s) sd[tid] += sd[tid + s];
        __syncthreads();
    }
    const float inv = 1.0f / sd[0];
    d_g[b*T + tid]       = e0 * inv;
    d_g[b*T + 256 + tid] = e1 * inv;
}

// ---------------- K5: GRU recurrence — Ur in REGISTERS, Uh in SMEM ----------------
// h/rh stored as PLAIN half[256]; each warp fetches its 16 k-values with two
// broadcast LDS.128 and builds duplicated-pair half2 via ALU dup ops (saves
// ~450 LDS-port cyc/step vs per-k broadcast loads).
__device__ __forceinline__ void drain8(
    __half2 aE0, __half2 aE1, __half2 aE2, __half2 aE3,
    __half2 aO0, __half2 aO1, __half2 aO2, __half2 aO3,
    float* __restrict__ redrow)
{
    float2 e0 = __half22float2(aE0), o0 = __half22float2(aO0);
    float2 e1 = __half22float2(aE1), o1 = __half22float2(aO1);
    float2 e2 = __half22float2(aE2), o2 = __half22float2(aO2);
    float2 e3 = __half22float2(aE3), o3 = __half22float2(aO3);
    *(float4*)redrow       = make_float4(e0.x+o0.x, e0.y+o0.y, e1.x+o1.x, e1.y+o1.y);
    *(float4*)(redrow + 4) = make_float4(e2.x+o2.x, e2.y+o2.y, e3.x+o3.x, e3.y+o3.y);
}

__global__ __launch_bounds__(512) void recurrence_kernel(
    const int* __restrict__ input_len,
    const float* __restrict__ Ws, const float* __restrict__ bs,
    const float* __restrict__ We, const float* __restrict__ be,
    float* __restrict__ out)
{
    extern __shared__ __half Uh_s[];     // [H*H] fp16, 128 KB
    const int b   = blockIdx.x;
    const int tid = threadIdx.x;
    const int kg  = tid >> 5;            // warp = k-group
    const int jl  = tid & 31;
    const int j0  = jl * 8;
    const int k0  = kg * 16;

    __shared__ __half h_s16[H];          // plain h
    __shared__ __half rh_s16[H];         // plain r*h
    __shared__ float  red[16][H];        // 16 KB partials
    __shared__ float  redS[8], redE[8];

    uint4 wr[16];
#pragma unroll
    for (int kk = 0; kk < 16; ++kk)
        wr[kk] = *(const uint4*)(d_Ur16 + (k0 + kk) * H + j0);

    {
        const uint4* src = (const uint4*)d_Uh16;
        uint4* dst = (uint4*)Uh_s;
        for (int i = tid; i < H*H/8; i += 512) dst[i] = src[i];
    }
    if (tid < H) h_s16[tid] = __float2half(0.f);

    const int len = input_len[b];
    const float* __restrict__ xb = d_xrh + (size_t)b * T * (2*H);

    float ws2 = 0.f, we2 = 0.f, xr_c = 0.f, xh_c = 0.f, g_c = 0.f;
    float hj = 0.f, msb = 0.f, meb = 0.f;
    if (tid < H) {
        ws2  = Ws[H + tid];
        we2  = We[H + tid];
        xr_c = xb[tid];
        xh_c = xb[H + tid];
        g_c  = d_g[b*T];
    }
    if (tid == 0) { msb = d_ms[b] + bs[0]; meb = d_me[b] + be[0]; }
    __syncthreads();

    const __half* __restrict__ UhP = Uh_s + k0 * H + j0;
    const __half2 hz = __float2half2_rn(0.f);

    float xr_n = 0.f, xh_n = 0.f, g_n = 0.f;
    for (int t = 0; t < len; ++t) {
        // ---- p1: partial h @ Ur (weights in regs; h via 2 broadcast LDS.128)
        {
            uint4 hA = *(const uint4*)&h_s16[k0];       // h[k0..k0+7]
            uint4 hB = *(const uint4*)&h_s16[k0 + 8];   // h[k0+8..k0+15]
            const __half2* hp = (const __half2*)&hA;    // 4 packed pairs
            const __half2* hq = (const __half2*)&hB;
            __half2 hh[16];
#pragma unroll
            for (int i = 0; i < 4; ++i) {
                hh[2*i]     = __low2half2(hp[i]);
                hh[2*i + 1] = __high2half2(hp[i]);
                hh[8 + 2*i]     = __low2half2(hq[i]);
                hh[8 + 2*i + 1] = __high2half2(hq[i]);
            }
            __half2 aE0 = hz, aE1 = hz, aE2 = hz, aE3 = hz;
            __half2 aO0 = hz, aO1 = hz, aO2 = hz, aO3 = hz;
#pragma unroll
            for (int kk = 0; kk < 16; ++kk) {
                const uint4 w2v = wr[kk];
                const __half2 hk = hh[kk];
                __half2 w0 = *(const __half2*)&w2v.x, w1 = *(const __half2*)&w2v.y;
                __half2 w2 = *(const __half2*)&w2v.z, w3 = *(const __half2*)&w2v.w;
                if (kk & 1) {
                    aO0 = __hfma2(w0, hk, aO0); aO1 = __hfma2(w1, hk, aO1);
                    aO2 = __hfma2(w2, hk, aO2); aO3 = __hfma2(w3, hk, aO3);
                } else {
                    aE0 = __hfma2(w0, hk, aE0); aE1 = __hfma2(w1, hk, aE1);
                    aE2 = __hfma2(w2, hk, aE2); aE3 = __hfma2(w3, hk, aE3);
                }
            }
            drain8(aE0, aE1, aE2, aE3, aO0, aO1, aO2, aO3, &red[kg][j0]);
        }
        __syncthreads();

        // ---- p2: r = sigmoid(xr + sum), write plain rh
        if (tid < H) {
            float s = xr_c;
#pragma unroll
            for (int g = 0; g < 16; ++g) s += red[g][tid];
            const float r = 1.0f / (1.0f + expf(-s));
            rh_s16[tid] = __float2half(r * hj);
            const int tn = (t + 1 < T) ? (t + 1) : (T - 1);
            xr_n = xb[tn*(2*H) + tid];
            xh_n = xb[tn*(2*H) + H + tid];
            g_n  = d_g[b*T + tn];
        }
        __syncthreads();

        // ---- p3: partial rh @ Uh (smem weights; rh via 2 broadcast LDS.128)
        {
            uint4 hA = *(const uint4*)&rh_s16[k0];
            uint4 hB = *(const uint4*)&rh_s16[k0 + 8];
            const __half2* hp = (const __half2*)&hA;
            const __half2* hq = (const __half2*)&hB;
            __half2 hh[16];
#pragma unroll
            for (int i = 0; i < 4; ++i) {
                hh[2*i]     = __low2half2(hp[i]);
                hh[2*i + 1] = __high2half2(hp[i]);
                hh[8 + 2*i]     = __low2half2(hq[i]);
                hh[8 + 2*i + 1] = __high2half2(hq[i]);
            }
            __half2 aE0 = hz, aE1 = hz, aE2 = hz, aE3 = hz;
            __half2 aO0 = hz, aO1 = hz, aO2 = hz, aO3 = hz;
#pragma unroll
            for (int kk = 0; kk < 16; ++kk) {
                const uint4 w2v = *(const uint4*)(UhP + kk * H);
                const __half2 hk = hh[kk];
                __half2 w0 = *(const __half2*)&w2v.x, w1 = *(const __half2*)&w2v.y;
                __half2 w2 = *(const __half2*)&w2v.z, w3 = *(const __half2*)&w2v.w;
                if (kk & 1) {
                    aO0 = __hfma2(w0, hk, aO0); aO1 = __hfma2(w1, hk, aO1);
                    aO2 = __hfma2(w2, hk, aO2); aO3 = __hfma2(w3, hk, aO3);
                } else {
                    aE0 = __hfma2(w0, hk, aE0); aE1 = __hfma2(w1, hk, aE1);
                    aE2 = __hfma2(w2, hk, aE2); aE3 = __hfma2(w3, hk, aE3);
                }
            }
            drain8(aE0, aE1, aE2, aE3, aO0, aO1, aO2, aO3, &red[kg][j0]);
        }
        __syncthreads();

        // ---- p4: h update + fused output dots
        if (tid < H) {
            float s = xh_c;
#pragma unroll
            for (int g = 0; g < 16; ++g) s += red[g][tid];
            const float hc = tanhf(s);
            const float hn = fmaf(g_c, hc - hj, hj);
            hj = hn;
            h_s16[tid] = __float2half(hn);
            float ps = hn * ws2, pe = hn * we2;
#pragma unroll
            for (int off = 16; off; off >>= 1) {
                ps += __shfl_xor_sync(0xffffffffu, ps, off);
                pe += __shfl_xor_sync(0xffffffffu, pe, off);
            }
            if (jl == 0) { redS[tid >> 5] = ps; redE[tid >> 5] = pe; }
            xr_c = xr_n; xh_c = xh_n; g_c = g_n;
        }
        __syncthreads();

        if (tid == 0) {
            float s = 0.f, se = 0.f;
#pragma unroll
            for (int w = 0; w < 8; ++w) { s += redS[w]; se += redE[w]; }
            out[b*T + t]       = tanhf(msb + s);
            out[B*T + b*T + t] = tanhf(meb + se);
        }
    }

    {
        const float cs = tanhf(d_ms[b] + bs[0]);
        const float ce = tanhf(d_me[b] + be[0]);
        for (int i = len + tid; i < T; i += 512) {
            out[b*T + i]       = cs;
            out[B*T + b*T + i] = ce;
        }
    }
}

// ---------------- entry point ----------------
extern "C" void kernel_launch(void* const* d_in, const int* in_sizes, int n_in,
                              void* d_out, int out_size)
{
    const float* qv   = (const float*)d_in[0];
    const float* fact = (const float*)d_in[1];
    const int*   ilen = (const int*)  d_in[2];
    const float* W1   = (const float*)d_in[3];
    const float* b1   = (const float*)d_in[4];
    const float* W2   = (const float*)d_in[5];
    const float* Wr   = (const float*)d_in[7];
    const float* Ur   = (const float*)d_in[8];
    const float* br   = (const float*)d_in[9];
    const float* Wh   = (const float*)d_in[10];
    const float* Uh   = (const float*)d_in[11];
    const float* bh   = (const float*)d_in[12];
    const float* Ws   = (const float*)d_in[13];
    const float* bs   = (const float*)d_in[14];
    const float* We   = (const float*)d_in[15];
    const float* be   = (const float*)d_in[16];
    float* out = (float*)d_out;

    const int uh_smem = H * H * (int)sizeof(__half);   // 128 KB dynamic

    static cudaStream_t s1 = nullptr, s2 = nullptr;
    static cudaEvent_t ev0, ev1, ev2;
    if (!s1) {
        cudaStreamCreateWithFlags(&s1, cudaStreamNonBlocking);
        cudaStreamCreateWithFlags(&s2, cudaStreamNonBlocking);
        cudaEventCreateWithFlags(&ev0, cudaEventDisableTiming);
        cudaEventCreateWithFlags(&ev1, cudaEventDisableTiming);
        cudaEventCreateWithFlags(&ev2, cudaEventDisableTiming);
        cudaFuncSetAttribute(recurrence_kernel,
                             cudaFuncAttributeMaxDynamicSharedMemorySize, uh_smem);
    }

    // fork
    cudaEventRecord(ev0, 0);
    cudaStreamWaitEvent(s1, ev0, 0);
    cudaStreamWaitEvent(s2, ev0, 0);

    // chain 1: xrh
    prep_u16_kernel<<<256, 256, 0, s1>>>(Ur, Uh, Wr, Wh);
    gemm_xrh_mma<<<dim3(256, 8), 256, 0, s1>>>(fact, br, bh);
    cudaEventRecord(ev1, s1);

    // chain 2: attention -> gates
    prep_w_kernel<<<256, 256, 0, s2>>>(W1);
    prep_batch_kernel<<<64, 256, 0, s2>>>(qv, W1, b1, Ws, We);
    gemm_att_mma<<<dim3(256, 4), 256, 0, s2>>>(fact, qv, W2);
    softmax_kernel<<<64, 256, 0, s2>>>();
    cudaEventRecord(ev2, s2);

    // join -> recurrence
    cudaStreamWaitEvent(0, ev1, 0);
    cudaStreamWaitEvent(0, ev2, 0);
    recurrence_kernel<<<64, 512, uh_smem>>>(ilen, Ws, bs, We, be, out);
}